// round 1
// baseline (speedup 1.0000x reference)
#include <cuda_runtime.h>
#include <cuda_bf16.h>
#include <cstdint>
#include <cstddef>

#define BATCH 2
#define SEQ   2048
#define DIM   1024
#define NHEAD 16
#define HD    64
#define SCALE 0.125f   // 64^-0.5

// Scratch (allocation-free rule: __device__ globals)
__device__ float g_qkv[(size_t)BATCH * SEQ * 3 * DIM];   // 48 MB
__device__ float g_attn[(size_t)BATCH * SEQ * DIM];      // 16 MB

// ---------------------------------------------------------------------------
// Tiled SGEMM: C[M,N] = A[M,K] @ B[K,N], all row-major, M%128==0, N%128==0, K%8==0
// 256 threads, BM=BN=128, BK=8, 8x8 microtile per thread.
// ---------------------------------------------------------------------------
__global__ __launch_bounds__(256) void sgemm128(
    const float* __restrict__ A, const float* __restrict__ Bm,
    float* __restrict__ C, int M, int N, int K)
{
    __shared__ float As[8][132];   // transposed A tile, padded
    __shared__ float Bs[8][128];

    const int t  = threadIdx.x;
    const int tx = t & 15;         // 0..15  (col group)
    const int ty = t >> 4;         // 0..15  (row group)
    const int rowBase = blockIdx.y * 128;
    const int colBase = blockIdx.x * 128;

    const int aRow = t >> 1;          // 0..127
    const int aK   = (t & 1) * 4;     // 0 or 4
    const int bRow = t >> 5;          // 0..7
    const int bCol = (t & 31) * 4;    // 0..124

    const float* Aptr = A + (size_t)(rowBase + aRow) * K + aK;
    const float* Bptr = Bm + (size_t)bRow * N + colBase + bCol;

    float acc[8][8];
    #pragma unroll
    for (int i = 0; i < 8; i++)
        #pragma unroll
        for (int j = 0; j < 8; j++) acc[i][j] = 0.f;

    for (int k0 = 0; k0 < K; k0 += 8) {
        float4 av = *(const float4*)Aptr;  Aptr += 8;
        float4 bv = *(const float4*)Bptr;  Bptr += (size_t)8 * N;

        As[aK + 0][aRow] = av.x;
        As[aK + 1][aRow] = av.y;
        As[aK + 2][aRow] = av.z;
        As[aK + 3][aRow] = av.w;
        *(float4*)&Bs[bRow][bCol] = bv;
        __syncthreads();

        #pragma unroll
        for (int k = 0; k < 8; k++) {
            float a[8], b[8];
            *(float4*)(a)     = *(const float4*)&As[k][ty * 8];
            *(float4*)(a + 4) = *(const float4*)&As[k][ty * 8 + 4];
            *(float4*)(b)     = *(const float4*)&Bs[k][tx * 8];
            *(float4*)(b + 4) = *(const float4*)&Bs[k][tx * 8 + 4];
            #pragma unroll
            for (int i = 0; i < 8; i++)
                #pragma unroll
                for (int j = 0; j < 8; j++)
                    acc[i][j] += a[i] * b[j];
        }
        __syncthreads();
    }

    #pragma unroll
    for (int i = 0; i < 8; i++) {
        float* cp = C + (size_t)(rowBase + ty * 8 + i) * N + colBase + tx * 8;
        float4 v0 = make_float4(acc[i][0], acc[i][1], acc[i][2], acc[i][3]);
        float4 v1 = make_float4(acc[i][4], acc[i][5], acc[i][6], acc[i][7]);
        *(float4*)(cp)     = v0;
        *(float4*)(cp + 4) = v1;
    }
}

// ---------------------------------------------------------------------------
// Flash attention: one block = 64 query rows of one (b,h).
// 128 threads; Bq=64, Bc=64, HD=64.
// Dynamic smem: Qt[64][68] + Kt[64][68] + Vs[64][68] + Ps[64][65] + stats
// ---------------------------------------------------------------------------
__global__ __launch_bounds__(128) void flash_kernel(
    const float* __restrict__ qkv, float* __restrict__ attn_out)
{
    extern __shared__ float sm[];
    float* Qt  = sm;                 // [64][68], Qt[d*68 + r] = q(q0+r, d)
    float* Kt  = Qt + 64 * 68;       // [64][68], Kt[d*68 + c] = k(c0+c, d)
    float* Vs  = Kt + 64 * 68;       // [64][68], Vs[c*68 + d] = v(c0+c, d)
    float* Ps  = Vs + 64 * 68;       // [64][65]
    float* m_s = Ps + 64 * 65;       // [64]
    float* l_s = m_s + 64;           // [64]
    float* fs  = l_s + 64;           // [64]

    const int t  = threadIdx.x;      // 0..127
    const int tx = t & 7;            // col group (8 cols)
    const int ty = t >> 3;           // row group (4 rows)
    const int h  = blockIdx.y;
    const int b  = blockIdx.z;
    const int q0 = blockIdx.x * 64;

    const int lr  = t >> 1;          // 0..63 loader row
    const int ld0 = (t & 1) * 32;    // 0 or 32

    // Load Q tile (transposed into smem), once.
    {
        const float* gq = qkv + ((size_t)(b * SEQ + q0 + lr) * 3 + 0) * DIM + h * HD + ld0;
        #pragma unroll
        for (int i = 0; i < 32; i += 4) {
            float4 v = *(const float4*)(gq + i);
            Qt[(ld0 + i + 0) * 68 + lr] = v.x;
            Qt[(ld0 + i + 1) * 68 + lr] = v.y;
            Qt[(ld0 + i + 2) * 68 + lr] = v.z;
            Qt[(ld0 + i + 3) * 68 + lr] = v.w;
        }
    }
    if (t < 64) { m_s[t] = -1e30f; l_s[t] = 0.f; }

    float o[4][8];
    #pragma unroll
    for (int i = 0; i < 4; i++)
        #pragma unroll
        for (int j = 0; j < 8; j++) o[i][j] = 0.f;

    for (int c0 = 0; c0 < SEQ; c0 += 64) {
        __syncthreads();   // previous PV done before K/V overwrite; Qt load done (1st iter)

        // Load K (transposed) and V tiles
        {
            const float* gk = qkv + ((size_t)(b * SEQ + c0 + lr) * 3 + 1) * DIM + h * HD + ld0;
            #pragma unroll
            for (int i = 0; i < 32; i += 4) {
                float4 v = *(const float4*)(gk + i);
                Kt[(ld0 + i + 0) * 68 + lr] = v.x;
                Kt[(ld0 + i + 1) * 68 + lr] = v.y;
                Kt[(ld0 + i + 2) * 68 + lr] = v.z;
                Kt[(ld0 + i + 3) * 68 + lr] = v.w;
            }
            const float* gv = qkv + ((size_t)(b * SEQ + c0 + lr) * 3 + 2) * DIM + h * HD + ld0;
            #pragma unroll
            for (int i = 0; i < 32; i += 4)
                *(float4*)&Vs[lr * 68 + ld0 + i] = *(const float4*)(gv + i);
        }
        __syncthreads();

        // Scores: sa[i][j] = sum_d q(ty*4+i, d) * k(tx*8+j, d)
        float sa[4][8];
        #pragma unroll
        for (int i = 0; i < 4; i++)
            #pragma unroll
            for (int j = 0; j < 8; j++) sa[i][j] = 0.f;

        #pragma unroll 8
        for (int d = 0; d < 64; d++) {
            float4 aq = *(const float4*)&Qt[d * 68 + ty * 4];
            float4 k0v = *(const float4*)&Kt[d * 68 + tx * 8];
            float4 k1v = *(const float4*)&Kt[d * 68 + tx * 8 + 4];
            float a[4] = {aq.x, aq.y, aq.z, aq.w};
            float kk[8] = {k0v.x, k0v.y, k0v.z, k0v.w, k1v.x, k1v.y, k1v.z, k1v.w};
            #pragma unroll
            for (int i = 0; i < 4; i++)
                #pragma unroll
                for (int j = 0; j < 8; j++)
                    sa[i][j] += a[i] * kk[j];
        }
        #pragma unroll
        for (int i = 0; i < 4; i++)
            #pragma unroll
            for (int j = 0; j < 8; j++)
                Ps[(ty * 4 + i) * 65 + tx * 8 + j] = sa[i][j] * SCALE;
        __syncthreads();

        // Online softmax: one thread per row (t < 64)
        if (t < 64) {
            float* prow = &Ps[t * 65];
            float mold = m_s[t];
            float mx = mold;
            #pragma unroll 8
            for (int c = 0; c < 64; c++) mx = fmaxf(mx, prow[c]);
            float f = __expf(mold - mx);
            float sum = 0.f;
            #pragma unroll 8
            for (int c = 0; c < 64; c++) {
                float e = __expf(prow[c] - mx);
                prow[c] = e;
                sum += e;
            }
            l_s[t] = l_s[t] * f + sum;
            m_s[t] = mx;
            fs[t]  = f;
        }
        __syncthreads();

        // Rescale O, then O += P @ V
        {
            float fr[4];
            #pragma unroll
            for (int i = 0; i < 4; i++) fr[i] = fs[ty * 4 + i];
            #pragma unroll
            for (int i = 0; i < 4; i++)
                #pragma unroll
                for (int j = 0; j < 8; j++) o[i][j] *= fr[i];
        }
        #pragma unroll 8
        for (int c = 0; c < 64; c++) {
            float p[4];
            #pragma unroll
            for (int i = 0; i < 4; i++) p[i] = Ps[(ty * 4 + i) * 65 + c];
            float4 v0 = *(const float4*)&Vs[c * 68 + tx * 8];
            float4 v1 = *(const float4*)&Vs[c * 68 + tx * 8 + 4];
            float vv[8] = {v0.x, v0.y, v0.z, v0.w, v1.x, v1.y, v1.z, v1.w};
            #pragma unroll
            for (int i = 0; i < 4; i++)
                #pragma unroll
                for (int j = 0; j < 8; j++)
                    o[i][j] += p[i] * vv[j];
        }
    }

    // Finalize: divide by l, write to attn buffer [b, s, h*64 + d]
    #pragma unroll
    for (int i = 0; i < 4; i++) {
        int row = ty * 4 + i;
        float inv = 1.f / l_s[row];
        float* op = attn_out + (size_t)(b * SEQ + q0 + row) * DIM + h * HD + tx * 8;
        float4 w0 = make_float4(o[i][0] * inv, o[i][1] * inv, o[i][2] * inv, o[i][3] * inv);
        float4 w1 = make_float4(o[i][4] * inv, o[i][5] * inv, o[i][6] * inv, o[i][7] * inv);
        *(float4*)(op)     = w0;
        *(float4*)(op + 4) = w1;
    }
}

// ---------------------------------------------------------------------------
extern "C" void kernel_launch(void* const* d_in, const int* in_sizes, int n_in,
                              void* d_out, int out_size)
{
    const float* x     = (const float*)d_in[0];   // [B,S,DIM]
    const float* Wqkv  = (const float*)d_in[1];   // [DIM, 3*DIM]
    const float* Wproj = (const float*)d_in[2];   // [DIM, DIM]
    float* out = (float*)d_out;                   // [B,S,DIM]

    float* qkv;  cudaGetSymbolAddress((void**)&qkv,  g_qkv);
    float* attn; cudaGetSymbolAddress((void**)&attn, g_attn);

    const int M = BATCH * SEQ;          // 4096

    // 1) qkv = x @ Wqkv   (M x 3072, K=1024)
    {
        dim3 grid(3 * DIM / 128, M / 128);
        sgemm128<<<grid, 256>>>(x, Wqkv, qkv, M, 3 * DIM, DIM);
    }

    // 2) flash attention
    {
        static bool attr_set = false;
        size_t smem = (size_t)(3 * 64 * 68 + 64 * 65 + 3 * 64) * sizeof(float);
        cudaFuncSetAttribute(flash_kernel, cudaFuncAttributeMaxDynamicSharedMemorySize, (int)smem);
        dim3 grid(SEQ / 64, NHEAD, BATCH);
        flash_kernel<<<grid, 128, smem>>>(qkv, attn);
        (void)attr_set;
    }

    // 3) out = attn @ Wproj  (M x 1024, K=1024)
    {
        dim3 grid(DIM / 128, M / 128);
        sgemm128<<<grid, 256>>>(attn, Wproj, out, M, DIM, DIM);
    }
}

// round 4
// speedup vs baseline: 1.2923x; 1.2923x over previous
#include <cuda_runtime.h>
#include <cuda_bf16.h>
#include <cstdint>
#include <cstddef>

#define BATCH 2
#define SEQ   2048
#define DIM   1024
#define NHEAD 16
#define HD    64
#define SCALE 0.125f   // 64^-0.5

// ---------------------------------------------------------------------------
// Scratch (allocation-free rule: __device__ globals)
// ---------------------------------------------------------------------------
__device__ float g_qkv [(size_t)BATCH * SEQ * 3 * DIM];          // 48 MB fp32
__device__ float g_attn[(size_t)BATCH * SEQ * DIM];              // 16 MB fp32
__device__ __nv_bfloat16 g_xhi[(size_t)BATCH * SEQ * DIM];
__device__ __nv_bfloat16 g_xlo[(size_t)BATCH * SEQ * DIM];
__device__ __nv_bfloat16 g_ahi[(size_t)BATCH * SEQ * DIM];
__device__ __nv_bfloat16 g_alo[(size_t)BATCH * SEQ * DIM];
__device__ __nv_bfloat16 g_wqhi[(size_t)3 * DIM * DIM];          // [3072,1024] K-major
__device__ __nv_bfloat16 g_wqlo[(size_t)3 * DIM * DIM];
__device__ __nv_bfloat16 g_wphi[(size_t)DIM * DIM];              // [1024,1024] K-major
__device__ __nv_bfloat16 g_wplo[(size_t)DIM * DIM];

// ---------------------------------------------------------------------------
// Portable PTX helpers (NO 'a'-suffix features: mma.sync / ldmatrix / cp.async)
// ---------------------------------------------------------------------------
__device__ __forceinline__ uint32_t smem_u32(const void* p) {
    uint32_t a;
    asm("{ .reg .u64 t; cvta.to.shared.u64 t, %1; cvt.u32.u64 %0, t; }" : "=r"(a) : "l"(p));
    return a;
}
#define CPA16(dst, src) \
    asm volatile("cp.async.cg.shared.global [%0], [%1], 16;" :: "r"(dst), "l"(src) : "memory")
#define CP_COMMIT() asm volatile("cp.async.commit_group;" ::: "memory")
#define CP_WAIT0()  asm volatile("cp.async.wait_group 0;" ::: "memory")
#define CP_WAIT1()  asm volatile("cp.async.wait_group 1;" ::: "memory")

#define LDSM_X4(r, addr) \
    asm volatile("ldmatrix.sync.aligned.m8n8.x4.shared.b16 {%0,%1,%2,%3}, [%4];" \
        : "=r"((r)[0]), "=r"((r)[1]), "=r"((r)[2]), "=r"((r)[3]) : "r"(addr))

#define MMA16816(c, a, b) \
    asm volatile("mma.sync.aligned.m16n8k16.row.col.f32.bf16.bf16.f32 " \
        "{%0,%1,%2,%3}, {%4,%5,%6,%7}, {%8,%9}, {%0,%1,%2,%3};" \
        : "+f"((c)[0]), "+f"((c)[1]), "+f"((c)[2]), "+f"((c)[3]) \
        : "r"((a)[0]), "r"((a)[1]), "r"((a)[2]), "r"((a)[3]), "r"((b)[0]), "r"((b)[1]))

// SW64 swizzle for 64-byte smem rows (conflict-free ldmatrix + stores)
#define SWZ64(off) ((off) ^ (((off) >> 3) & 0x30))

// ---------------------------------------------------------------------------
// Preprocessing: fp32 -> (hi, lo) bf16 split, flat
// ---------------------------------------------------------------------------
__global__ __launch_bounds__(256) void split_kernel(
    const float* __restrict__ X, __nv_bfloat16* __restrict__ hi,
    __nv_bfloat16* __restrict__ lo, int n4)
{
    int i = blockIdx.x * blockDim.x + threadIdx.x;
    if (i >= n4) return;
    float4 v = ((const float4*)X)[i];
    __nv_bfloat16 h[4], l[4];
    float f[4] = {v.x, v.y, v.z, v.w};
    #pragma unroll
    for (int j = 0; j < 4; j++) {
        h[j] = __float2bfloat16(f[j]);
        l[j] = __float2bfloat16(f[j] - __bfloat162float(h[j]));
    }
    ((uint2*)hi)[i] = *(uint2*)h;
    ((uint2*)lo)[i] = *(uint2*)l;
}

// W [K, N] fp32 -> T [N, K] bf16 hi/lo (transpose + split)
__global__ __launch_bounds__(256) void transpose_split(
    const float* __restrict__ W, __nv_bfloat16* __restrict__ Thi,
    __nv_bfloat16* __restrict__ Tlo, int K, int N)
{
    __shared__ float tile[32][33];
    int tx = threadIdx.x & 31, ty = threadIdx.x >> 5;   // 32x8
    int k0 = blockIdx.y * 32, n0 = blockIdx.x * 32;
    #pragma unroll
    for (int i = 0; i < 32; i += 8)
        tile[ty + i][tx] = W[(size_t)(k0 + ty + i) * N + n0 + tx];
    __syncthreads();
    #pragma unroll
    for (int i = 0; i < 32; i += 8) {
        float v = tile[tx][ty + i];                     // (k0+tx, n0+ty+i)
        __nv_bfloat16 h = __float2bfloat16(v);
        __nv_bfloat16 l = __float2bfloat16(v - __bfloat162float(h));
        size_t o = (size_t)(n0 + ty + i) * K + k0 + tx;
        Thi[o] = h; Tlo[o] = l;
    }
}

// ---------------------------------------------------------------------------
// HMMA bf16-split GEMM: C[M,N] = A[M,K] @ T[N,K]^T  (fp32 out)
// CTA 128x128, BK=32, cp.async double buffer, 8 warps (4m x 2n), warp 32x64.
// Stage layout (32KB): Ahi[0,8K) Alo[8K,16K) Bhi[16K,24K) Blo[24K,32K)
// Rows are 64B (32 bf16) with SW64 swizzle.
// ---------------------------------------------------------------------------
#define GST 32768
#define GSMEM_TOTAL (2 * GST)

#define LOAD_STAGE(sidx, kc) do {                                              \
    uint32_t sb = sbase + (uint32_t)(sidx) * GST;                              \
    _Pragma("unroll")                                                          \
    for (int t_ = 0; t_ < 2; ++t_) {                                           \
        int v_ = tid + t_ * 256;                                               \
        int row_ = v_ >> 2, cb_ = v_ & 3;                                      \
        uint32_t sw_ = SWZ64((uint32_t)(row_ * 64 + cb_ * 16));                \
        size_t gA_ = (size_t)(rowBase + row_) * K + (kc) + cb_ * 8;            \
        size_t gB_ = (size_t)(colBase + row_) * K + (kc) + cb_ * 8;            \
        CPA16(sb + sw_,         (const char*)(Ahi + gA_));                     \
        CPA16(sb + 8192  + sw_, (const char*)(Alo + gA_));                     \
        CPA16(sb + 16384 + sw_, (const char*)(Bhi + gB_));                     \
        CPA16(sb + 24576 + sw_, (const char*)(Blo + gB_));                     \
    }                                                                          \
} while (0)

__global__ __launch_bounds__(256, 1) void gemm_mma(
    const __nv_bfloat16* __restrict__ Ahi, const __nv_bfloat16* __restrict__ Alo,
    const __nv_bfloat16* __restrict__ Bhi, const __nv_bfloat16* __restrict__ Blo,
    float* __restrict__ C, int M, int N, int K)
{
    extern __shared__ char smem[];
    const uint32_t sbase = smem_u32(smem);
    const int tid  = threadIdx.x;
    const int lane = tid & 31;
    const int wid  = tid >> 5;
    const int wm = (wid & 3) * 32;      // warp row offset in CTA tile
    const int wn = (wid >> 2) * 64;     // warp col offset
    const int rowBase = blockIdx.y * 128;
    const int colBase = blockIdx.x * 128;

    // ldmatrix per-lane offsets (within a 16-row x 64B tile slice)
    const int mi = lane >> 3;
    const uint32_t a_off = (uint32_t)((((mi & 1) * 8 + (lane & 7)) * 64) + (mi >> 1) * 16);
    const uint32_t b_off = (uint32_t)((((mi >> 1) * 8 + (lane & 7)) * 64) + (mi & 1) * 16);

    float acc[2][8][4];
    #pragma unroll
    for (int i = 0; i < 2; i++)
        #pragma unroll
        for (int j = 0; j < 8; j++)
            #pragma unroll
            for (int q = 0; q < 4; q++) acc[i][j][q] = 0.f;

    const int nk = K / 32;

    LOAD_STAGE(0, 0);
    CP_COMMIT();

    for (int c = 0; c < nk; ++c) {
        const int s = c & 1;
        if (c + 1 < nk) {
            LOAD_STAGE((c + 1) & 1, (c + 1) * 32);
            CP_COMMIT();
            CP_WAIT1();
        } else {
            CP_WAIT0();
        }
        __syncthreads();

        const uint32_t st = sbase + (uint32_t)s * GST;
        #pragma unroll
        for (int kb = 0; kb < 64; kb += 32) {           // kb = k-step byte offset
            uint32_t ahi[2][4], alo[2][4];
            #pragma unroll
            for (int i = 0; i < 2; i++) {
                uint32_t off = (uint32_t)((wm + i * 16) * 64 + kb) + a_off;
                LDSM_X4(ahi[i], st + SWZ64(off));
                LDSM_X4(alo[i], st + 8192 + SWZ64(off));
            }
            uint32_t bhi[4][4], blo[4][4];
            #pragma unroll
            for (int jj = 0; jj < 4; jj++) {
                uint32_t off = (uint32_t)((wn + jj * 16) * 64 + kb) + b_off;
                LDSM_X4(bhi[jj], st + 16384 + SWZ64(off));
                LDSM_X4(blo[jj], st + 24576 + SWZ64(off));
            }
            #pragma unroll
            for (int i = 0; i < 2; i++)
                #pragma unroll
                for (int j = 0; j < 8; j++) {
                    uint32_t* bh = &bhi[j >> 1][(j & 1) * 2];
                    uint32_t* bl = &blo[j >> 1][(j & 1) * 2];
                    MMA16816(acc[i][j], ahi[i], bh);
                    MMA16816(acc[i][j], ahi[i], bl);
                    MMA16816(acc[i][j], alo[i], bh);
                }
        }
        __syncthreads();
    }

    // epilogue: direct fp32 stores
    #pragma unroll
    for (int i = 0; i < 2; i++) {
        #pragma unroll
        for (int j = 0; j < 8; j++) {
            int r0 = rowBase + wm + i * 16 + (lane >> 2);
            int c0 = colBase + wn + j * 8 + (lane & 3) * 2;
            *(float2*)&C[(size_t)r0 * N + c0]       = make_float2(acc[i][j][0], acc[i][j][1]);
            *(float2*)&C[(size_t)(r0 + 8) * N + c0] = make_float2(acc[i][j][2], acc[i][j][3]);
        }
    }
}

// ---------------------------------------------------------------------------
// Flash attention (SIMT fp32, unchanged): one block = 64 query rows of one (b,h)
// ---------------------------------------------------------------------------
__global__ __launch_bounds__(128) void flash_kernel(
    const float* __restrict__ qkv, float* __restrict__ attn_out)
{
    extern __shared__ float sm[];
    float* Qt  = sm;                 // [64][68]
    float* Kt  = Qt + 64 * 68;       // [64][68]
    float* Vs  = Kt + 64 * 68;       // [64][68]
    float* Ps  = Vs + 64 * 68;       // [64][65]
    float* m_s = Ps + 64 * 65;
    float* l_s = m_s + 64;
    float* fs  = l_s + 64;

    const int t  = threadIdx.x;
    const int tx = t & 7;
    const int ty = t >> 3;
    const int h  = blockIdx.y;
    const int b  = blockIdx.z;
    const int q0 = blockIdx.x * 64;

    const int lr  = t >> 1;
    const int ld0 = (t & 1) * 32;

    {
        const float* gq = qkv + ((size_t)(b * SEQ + q0 + lr) * 3 + 0) * DIM + h * HD + ld0;
        #pragma unroll
        for (int i = 0; i < 32; i += 4) {
            float4 v = *(const float4*)(gq + i);
            Qt[(ld0 + i + 0) * 68 + lr] = v.x;
            Qt[(ld0 + i + 1) * 68 + lr] = v.y;
            Qt[(ld0 + i + 2) * 68 + lr] = v.z;
            Qt[(ld0 + i + 3) * 68 + lr] = v.w;
        }
    }
    if (t < 64) { m_s[t] = -1e30f; l_s[t] = 0.f; }

    float o[4][8];
    #pragma unroll
    for (int i = 0; i < 4; i++)
        #pragma unroll
        for (int j = 0; j < 8; j++) o[i][j] = 0.f;

    for (int c0 = 0; c0 < SEQ; c0 += 64) {
        __syncthreads();
        {
            const float* gk = qkv + ((size_t)(b * SEQ + c0 + lr) * 3 + 1) * DIM + h * HD + ld0;
            #pragma unroll
            for (int i = 0; i < 32; i += 4) {
                float4 v = *(const float4*)(gk + i);
                Kt[(ld0 + i + 0) * 68 + lr] = v.x;
                Kt[(ld0 + i + 1) * 68 + lr] = v.y;
                Kt[(ld0 + i + 2) * 68 + lr] = v.z;
                Kt[(ld0 + i + 3) * 68 + lr] = v.w;
            }
            const float* gv = qkv + ((size_t)(b * SEQ + c0 + lr) * 3 + 2) * DIM + h * HD + ld0;
            #pragma unroll
            for (int i = 0; i < 32; i += 4)
                *(float4*)&Vs[lr * 68 + ld0 + i] = *(const float4*)(gv + i);
        }
        __syncthreads();

        float sa[4][8];
        #pragma unroll
        for (int i = 0; i < 4; i++)
            #pragma unroll
            for (int j = 0; j < 8; j++) sa[i][j] = 0.f;

        #pragma unroll 8
        for (int d = 0; d < 64; d++) {
            float4 aq  = *(const float4*)&Qt[d * 68 + ty * 4];
            float4 k0v = *(const float4*)&Kt[d * 68 + tx * 8];
            float4 k1v = *(const float4*)&Kt[d * 68 + tx * 8 + 4];
            float a[4]  = {aq.x, aq.y, aq.z, aq.w};
            float kk[8] = {k0v.x, k0v.y, k0v.z, k0v.w, k1v.x, k1v.y, k1v.z, k1v.w};
            #pragma unroll
            for (int i = 0; i < 4; i++)
                #pragma unroll
                for (int j = 0; j < 8; j++)
                    sa[i][j] += a[i] * kk[j];
        }
        #pragma unroll
        for (int i = 0; i < 4; i++)
            #pragma unroll
            for (int j = 0; j < 8; j++)
                Ps[(ty * 4 + i) * 65 + tx * 8 + j] = sa[i][j] * SCALE;
        __syncthreads();

        if (t < 64) {
            float* prow = &Ps[t * 65];
            float mold = m_s[t];
            float mx = mold;
            #pragma unroll 8
            for (int c = 0; c < 64; c++) mx = fmaxf(mx, prow[c]);
            float f = __expf(mold - mx);
            float sum = 0.f;
            #pragma unroll 8
            for (int c = 0; c < 64; c++) {
                float e = __expf(prow[c] - mx);
                prow[c] = e;
                sum += e;
            }
            l_s[t] = l_s[t] * f + sum;
            m_s[t] = mx;
            fs[t]  = f;
        }
        __syncthreads();

        {
            float fr[4];
            #pragma unroll
            for (int i = 0; i < 4; i++) fr[i] = fs[ty * 4 + i];
            #pragma unroll
            for (int i = 0; i < 4; i++)
                #pragma unroll
                for (int j = 0; j < 8; j++) o[i][j] *= fr[i];
        }
        #pragma unroll 8
        for (int c = 0; c < 64; c++) {
            float p[4];
            #pragma unroll
            for (int i = 0; i < 4; i++) p[i] = Ps[(ty * 4 + i) * 65 + c];
            float4 v0 = *(const float4*)&Vs[c * 68 + tx * 8];
            float4 v1 = *(const float4*)&Vs[c * 68 + tx * 8 + 4];
            float vv[8] = {v0.x, v0.y, v0.z, v0.w, v1.x, v1.y, v1.z, v1.w};
            #pragma unroll
            for (int i = 0; i < 4; i++)
                #pragma unroll
                for (int j = 0; j < 8; j++)
                    o[i][j] += p[i] * vv[j];
        }
    }

    #pragma unroll
    for (int i = 0; i < 4; i++) {
        int row = ty * 4 + i;
        float inv = 1.f / l_s[row];
        float* op = attn_out + (size_t)(b * SEQ + q0 + row) * DIM + h * HD + tx * 8;
        *(float4*)(op)     = make_float4(o[i][0]*inv, o[i][1]*inv, o[i][2]*inv, o[i][3]*inv);
        *(float4*)(op + 4) = make_float4(o[i][4]*inv, o[i][5]*inv, o[i][6]*inv, o[i][7]*inv);
    }
}

// ---------------------------------------------------------------------------
extern "C" void kernel_launch(void* const* d_in, const int* in_sizes, int n_in,
                              void* d_out, int out_size)
{
    const float* x     = (const float*)d_in[0];   // [B,S,DIM]
    const float* Wqkv  = (const float*)d_in[1];   // [DIM, 3*DIM]
    const float* Wproj = (const float*)d_in[2];   // [DIM, DIM]
    float* out = (float*)d_out;                   // [B,S,DIM]

    float *qkv, *attn;
    __nv_bfloat16 *xhi, *xlo, *ahi, *alo, *wqhi, *wqlo, *wphi, *wplo;
    cudaGetSymbolAddress((void**)&qkv,  g_qkv);
    cudaGetSymbolAddress((void**)&attn, g_attn);
    cudaGetSymbolAddress((void**)&xhi,  g_xhi);
    cudaGetSymbolAddress((void**)&xlo,  g_xlo);
    cudaGetSymbolAddress((void**)&ahi,  g_ahi);
    cudaGetSymbolAddress((void**)&alo,  g_alo);
    cudaGetSymbolAddress((void**)&wqhi, g_wqhi);
    cudaGetSymbolAddress((void**)&wqlo, g_wqlo);
    cudaGetSymbolAddress((void**)&wphi, g_wphi);
    cudaGetSymbolAddress((void**)&wplo, g_wplo);

    const int M = BATCH * SEQ;          // 4096

    cudaFuncSetAttribute(gemm_mma, cudaFuncAttributeMaxDynamicSharedMemorySize, GSMEM_TOTAL);

    // 0) precision splits / transposed weights
    split_kernel<<<(M * DIM / 4 + 255) / 256, 256>>>(x, xhi, xlo, M * DIM / 4);
    {
        dim3 g1(3 * DIM / 32, DIM / 32);
        transpose_split<<<g1, 256>>>(Wqkv, wqhi, wqlo, DIM, 3 * DIM);
        dim3 g2(DIM / 32, DIM / 32);
        transpose_split<<<g2, 256>>>(Wproj, wphi, wplo, DIM, DIM);
    }

    // 1) qkv = x @ Wqkv  (HMMA tensor cores)
    {
        dim3 grid(3 * DIM / 128, M / 128);
        gemm_mma<<<grid, 256, GSMEM_TOTAL>>>(xhi, xlo, wqhi, wqlo, qkv, M, 3 * DIM, DIM);
    }

    // 2) flash attention (fp32 SIMT)
    {
        size_t smem = (size_t)(3 * 64 * 68 + 64 * 65 + 3 * 64) * sizeof(float);
        cudaFuncSetAttribute(flash_kernel, cudaFuncAttributeMaxDynamicSharedMemorySize, (int)smem);
        dim3 grid(SEQ / 64, NHEAD, BATCH);
        flash_kernel<<<grid, 128, smem>>>(qkv, attn);
    }

    // 3) out = attn @ Wproj  (HMMA tensor cores)
    split_kernel<<<(M * DIM / 4 + 255) / 256, 256>>>(attn, ahi, alo, M * DIM / 4);
    {
        dim3 grid(DIM / 128, M / 128);
        gemm_mma<<<grid, 256, GSMEM_TOTAL>>>(ahi, alo, wphi, wplo, out, M, DIM, DIM);
    }
}

// round 5
// speedup vs baseline: 3.6771x; 2.8453x over previous
#include <cuda_runtime.h>
#include <cuda_bf16.h>
#include <cstdint>
#include <cstddef>

#define BATCH 2
#define SEQ   2048
#define DIM   1024
#define NHEAD 16
#define HD    64
// SCALE * log2(e): logits kept in base-2 domain
#define SC2   0.18033688011112042f

// ---------------------------------------------------------------------------
// Scratch (allocation-free rule: __device__ globals)
// ---------------------------------------------------------------------------
__device__ __nv_bfloat16 g_xhi[(size_t)BATCH * SEQ * DIM];
__device__ __nv_bfloat16 g_xlo[(size_t)BATCH * SEQ * DIM];
__device__ __nv_bfloat16 g_qh [(size_t)BATCH * SEQ * 3 * DIM];   // qkv hi
__device__ __nv_bfloat16 g_ql [(size_t)BATCH * SEQ * 3 * DIM];   // qkv lo
__device__ __nv_bfloat16 g_ahi[(size_t)BATCH * SEQ * DIM];       // attn hi
__device__ __nv_bfloat16 g_alo[(size_t)BATCH * SEQ * DIM];       // attn lo
__device__ __nv_bfloat16 g_wqhi[(size_t)3 * DIM * DIM];          // [3072,1024] K-major
__device__ __nv_bfloat16 g_wqlo[(size_t)3 * DIM * DIM];
__device__ __nv_bfloat16 g_wphi[(size_t)DIM * DIM];
__device__ __nv_bfloat16 g_wplo[(size_t)DIM * DIM];

// ---------------------------------------------------------------------------
// Portable PTX helpers
// ---------------------------------------------------------------------------
__device__ __forceinline__ uint32_t smem_u32(const void* p) {
    uint32_t a;
    asm("{ .reg .u64 t; cvta.to.shared.u64 t, %1; cvt.u32.u64 %0, t; }" : "=r"(a) : "l"(p));
    return a;
}
#define CPA16(dst, src) \
    asm volatile("cp.async.cg.shared.global [%0], [%1], 16;" :: "r"(dst), "l"(src) : "memory")
#define CP_COMMIT() asm volatile("cp.async.commit_group;" ::: "memory")
#define CP_WAIT0()  asm volatile("cp.async.wait_group 0;" ::: "memory")
#define CP_WAIT1()  asm volatile("cp.async.wait_group 1;" ::: "memory")

#define LDSM_X4(r, addr) \
    asm volatile("ldmatrix.sync.aligned.m8n8.x4.shared.b16 {%0,%1,%2,%3}, [%4];" \
        : "=r"((r)[0]), "=r"((r)[1]), "=r"((r)[2]), "=r"((r)[3]) : "r"(addr))
#define LDSM_X4T(r, addr) \
    asm volatile("ldmatrix.sync.aligned.m8n8.x4.trans.shared.b16 {%0,%1,%2,%3}, [%4];" \
        : "=r"((r)[0]), "=r"((r)[1]), "=r"((r)[2]), "=r"((r)[3]) : "r"(addr))

#define MMA16816(c, a, b) \
    asm volatile("mma.sync.aligned.m16n8k16.row.col.f32.bf16.bf16.f32 " \
        "{%0,%1,%2,%3}, {%4,%5,%6,%7}, {%8,%9}, {%0,%1,%2,%3};" \
        : "+f"((c)[0]), "+f"((c)[1]), "+f"((c)[2]), "+f"((c)[3]) \
        : "r"((a)[0]), "r"((a)[1]), "r"((a)[2]), "r"((a)[3]), "r"((b)[0]), "r"((b)[1]))

#define SWZ64(off)  ((off) ^ (((off) >> 3) & 0x30))
#define SWZ128(off) ((off) ^ (((off) >> 3) & 0x70))

__device__ __forceinline__ float ex2f(float x) {
    float y; asm("ex2.approx.ftz.f32 %0, %1;" : "=f"(y) : "f"(x)); return y;
}
__device__ __forceinline__ uint32_t pack_bf2(float lo, float hi) {
    __nv_bfloat162 h = __floats2bfloat162_rn(lo, hi);
    return *(uint32_t*)&h;
}

// ---------------------------------------------------------------------------
// Preprocessing
// ---------------------------------------------------------------------------
__global__ __launch_bounds__(256) void split_kernel(
    const float* __restrict__ X, __nv_bfloat16* __restrict__ hi,
    __nv_bfloat16* __restrict__ lo, int n4)
{
    int i = blockIdx.x * blockDim.x + threadIdx.x;
    if (i >= n4) return;
    float4 v = ((const float4*)X)[i];
    __nv_bfloat16 h[4], l[4];
    float f[4] = {v.x, v.y, v.z, v.w};
    #pragma unroll
    for (int j = 0; j < 4; j++) {
        h[j] = __float2bfloat16(f[j]);
        l[j] = __float2bfloat16(f[j] - __bfloat162float(h[j]));
    }
    ((uint2*)hi)[i] = *(uint2*)h;
    ((uint2*)lo)[i] = *(uint2*)l;
}

__global__ __launch_bounds__(256) void transpose_split(
    const float* __restrict__ W, __nv_bfloat16* __restrict__ Thi,
    __nv_bfloat16* __restrict__ Tlo, int K, int N)
{
    __shared__ float tile[32][33];
    int tx = threadIdx.x & 31, ty = threadIdx.x >> 5;
    int k0 = blockIdx.y * 32, n0 = blockIdx.x * 32;
    #pragma unroll
    for (int i = 0; i < 32; i += 8)
        tile[ty + i][tx] = W[(size_t)(k0 + ty + i) * N + n0 + tx];
    __syncthreads();
    #pragma unroll
    for (int i = 0; i < 32; i += 8) {
        float v = tile[tx][ty + i];
        __nv_bfloat16 h = __float2bfloat16(v);
        __nv_bfloat16 l = __float2bfloat16(v - __bfloat162float(h));
        size_t o = (size_t)(n0 + ty + i) * K + k0 + tx;
        Thi[o] = h; Tlo[o] = l;
    }
}

// ---------------------------------------------------------------------------
// HMMA bf16-split GEMM: C = A[M,K] @ T[N,K]^T, fp32 or bf16-hi/lo output
// ---------------------------------------------------------------------------
#define GST 32768
#define GSMEM_TOTAL (2 * GST)

#define LOAD_STAGE(sidx, kc) do {                                              \
    uint32_t sb = sbase + (uint32_t)(sidx) * GST;                              \
    _Pragma("unroll")                                                          \
    for (int t_ = 0; t_ < 2; ++t_) {                                           \
        int v_ = tid + t_ * 256;                                               \
        int row_ = v_ >> 2, cb_ = v_ & 3;                                      \
        uint32_t sw_ = SWZ64((uint32_t)(row_ * 64 + cb_ * 16));                \
        size_t gA_ = (size_t)(rowBase + row_) * K + (kc) + cb_ * 8;            \
        size_t gB_ = (size_t)(colBase + row_) * K + (kc) + cb_ * 8;            \
        CPA16(sb + sw_,         (const char*)(Ahi + gA_));                     \
        CPA16(sb + 8192  + sw_, (const char*)(Alo + gA_));                     \
        CPA16(sb + 16384 + sw_, (const char*)(Bhi + gB_));                     \
        CPA16(sb + 24576 + sw_, (const char*)(Blo + gB_));                     \
    }                                                                          \
} while (0)

template <bool SPLIT>
__global__ __launch_bounds__(256, 1) void gemm_mma(
    const __nv_bfloat16* __restrict__ Ahi, const __nv_bfloat16* __restrict__ Alo,
    const __nv_bfloat16* __restrict__ Bhi, const __nv_bfloat16* __restrict__ Blo,
    float* __restrict__ C, __nv_bfloat16* __restrict__ Chi,
    __nv_bfloat16* __restrict__ Clo, int M, int N, int K)
{
    extern __shared__ char smem[];
    const uint32_t sbase = smem_u32(smem);
    const int tid  = threadIdx.x;
    const int lane = tid & 31;
    const int wid  = tid >> 5;
    const int wm = (wid & 3) * 32;
    const int wn = (wid >> 2) * 64;
    const int rowBase = blockIdx.y * 128;
    const int colBase = blockIdx.x * 128;

    const int mi = lane >> 3;
    const uint32_t a_off = (uint32_t)((((mi & 1) * 8 + (lane & 7)) * 64) + (mi >> 1) * 16);
    const uint32_t b_off = (uint32_t)((((mi >> 1) * 8 + (lane & 7)) * 64) + (mi & 1) * 16);

    float acc[2][8][4];
    #pragma unroll
    for (int i = 0; i < 2; i++)
        #pragma unroll
        for (int j = 0; j < 8; j++)
            #pragma unroll
            for (int q = 0; q < 4; q++) acc[i][j][q] = 0.f;

    const int nk = K / 32;
    LOAD_STAGE(0, 0);
    CP_COMMIT();

    for (int c = 0; c < nk; ++c) {
        const int s = c & 1;
        if (c + 1 < nk) { LOAD_STAGE((c + 1) & 1, (c + 1) * 32); CP_COMMIT(); CP_WAIT1(); }
        else           { CP_WAIT0(); }
        __syncthreads();

        const uint32_t st = sbase + (uint32_t)s * GST;
        #pragma unroll
        for (int kb = 0; kb < 64; kb += 32) {
            uint32_t ahi[2][4], alo[2][4];
            #pragma unroll
            for (int i = 0; i < 2; i++) {
                uint32_t off = (uint32_t)((wm + i * 16) * 64 + kb) + a_off;
                LDSM_X4(ahi[i], st + SWZ64(off));
                LDSM_X4(alo[i], st + 8192 + SWZ64(off));
            }
            uint32_t bhi[4][4], blo[4][4];
            #pragma unroll
            for (int jj = 0; jj < 4; jj++) {
                uint32_t off = (uint32_t)((wn + jj * 16) * 64 + kb) + b_off;
                LDSM_X4(bhi[jj], st + 16384 + SWZ64(off));
                LDSM_X4(blo[jj], st + 24576 + SWZ64(off));
            }
            #pragma unroll
            for (int i = 0; i < 2; i++)
                #pragma unroll
                for (int j = 0; j < 8; j++) {
                    uint32_t* bh = &bhi[j >> 1][(j & 1) * 2];
                    uint32_t* bl = &blo[j >> 1][(j & 1) * 2];
                    MMA16816(acc[i][j], ahi[i], bh);
                    MMA16816(acc[i][j], ahi[i], bl);
                    MMA16816(acc[i][j], alo[i], bh);
                }
        }
        __syncthreads();
    }

    #pragma unroll
    for (int i = 0; i < 2; i++) {
        #pragma unroll
        for (int j = 0; j < 8; j++) {
            int r0 = rowBase + wm + i * 16 + (lane >> 2);
            int c0 = colBase + wn + j * 8 + (lane & 3) * 2;
            if (SPLIT) {
                #pragma unroll
                for (int hh = 0; hh < 2; hh++) {
                    float v0 = acc[i][j][hh * 2], v1 = acc[i][j][hh * 2 + 1];
                    __nv_bfloat162 h2 = __floats2bfloat162_rn(v0, v1);
                    float l0 = v0 - __bfloat162float(h2.x);
                    float l1 = v1 - __bfloat162float(h2.y);
                    size_t idx = ((size_t)(r0 + hh * 8) * N + c0) >> 1;
                    ((uint32_t*)Chi)[idx] = *(uint32_t*)&h2;
                    ((uint32_t*)Clo)[idx] = pack_bf2(l0, l1);
                }
            } else {
                *(float2*)&C[(size_t)r0 * N + c0]       = make_float2(acc[i][j][0], acc[i][j][1]);
                *(float2*)&C[(size_t)(r0 + 8) * N + c0] = make_float2(acc[i][j][2], acc[i][j][3]);
            }
        }
    }
}

// ---------------------------------------------------------------------------
// Flash attention, HMMA. CTA = 128 q rows of one (b,h); 8 warps x 16 rows.
// smem: 2 stages x [Khi|Klo|Vhi|Vlo] (16KB each) + Qhi|Qlo (16KB each) =160KB
// ---------------------------------------------------------------------------
#define FST     65536
#define F_KHI   0
#define F_KLO   16384
#define F_VHI   32768
#define F_VLO   49152
#define FQ_OFF  (2 * FST)
#define FSMEM_TOTAL (2 * FST + 32768)

#define FLOAD_KV(sidx, c0b) do {                                               \
    uint32_t sb = sbase + (uint32_t)(sidx) * FST;                              \
    _Pragma("unroll")                                                          \
    for (int t_ = 0; t_ < 4; ++t_) {                                           \
        int v_ = tid + t_ * 256;                                               \
        int row_ = v_ >> 3, ch_ = v_ & 7;                                      \
        uint32_t sw_ = SWZ128((uint32_t)(row_ * 128 + ch_ * 16));              \
        size_t base_ = ((size_t)(bS + (c0b) + row_) * 3) * DIM + hHD + ch_ * 8;\
        CPA16(sb + F_KHI + sw_, (const char*)(qh + base_ + DIM));              \
        CPA16(sb + F_KLO + sw_, (const char*)(ql + base_ + DIM));              \
        CPA16(sb + F_VHI + sw_, (const char*)(qh + base_ + 2 * DIM));          \
        CPA16(sb + F_VLO + sw_, (const char*)(ql + base_ + 2 * DIM));          \
    }                                                                          \
} while (0)

__global__ __launch_bounds__(256, 1) void flash_mma(
    const __nv_bfloat16* __restrict__ qh, const __nv_bfloat16* __restrict__ ql,
    __nv_bfloat16* __restrict__ Ahi, __nv_bfloat16* __restrict__ Alo)
{
    extern __shared__ char smem[];
    const uint32_t sbase = smem_u32(smem);
    const int tid  = threadIdx.x;
    const int lane = tid & 31;
    const int wid  = tid >> 5;
    const int wrow = wid * 16;                 // warp's q-row offset in 128-tile
    const int h  = blockIdx.y;
    const int b  = blockIdx.z;
    const int q0 = blockIdx.x * 128;
    const int bS  = b * SEQ;
    const int hHD = h * HD;

    const int mi = lane >> 3;
    const uint32_t a_row = (mi & 1) * 8 + (lane & 7);   // A / V-trans row pattern
    const uint32_t a_ch  = (mi >> 1) * 16;
    const uint32_t b_row = (mi >> 1) * 8 + (lane & 7);  // B (K) row pattern
    const uint32_t b_ch  = (mi & 1) * 16;

    // Q tile load (once) + first KV stage, one commit group
    {
        #pragma unroll
        for (int t_ = 0; t_ < 4; ++t_) {
            int v_ = tid + t_ * 256;
            int row_ = v_ >> 3, ch_ = v_ & 7;
            uint32_t sw_ = SWZ128((uint32_t)(row_ * 128 + ch_ * 16));
            size_t base_ = ((size_t)(bS + q0 + row_) * 3) * DIM + hHD + ch_ * 8;
            CPA16(sbase + FQ_OFF + sw_,         (const char*)(qh + base_));
            CPA16(sbase + FQ_OFF + 16384 + sw_, (const char*)(ql + base_));
        }
        FLOAD_KV(0, 0);
        CP_COMMIT();
    }

    float S[16][4];
    float O[8][4];
    #pragma unroll
    for (int j = 0; j < 8; j++)
        #pragma unroll
        for (int q = 0; q < 4; q++) O[j][q] = 0.f;
    float mA = -1e30f, mB = -1e30f, lA = 0.f, lB = 0.f;

    const int ntiles = SEQ / 128;   // 16

    for (int tI = 0; tI < ntiles; ++tI) {
        const int s = tI & 1;
        if (tI + 1 < ntiles) { FLOAD_KV((tI + 1) & 1, (tI + 1) * 128); CP_COMMIT(); CP_WAIT1(); }
        else                 { CP_WAIT0(); }
        __syncthreads();

        const uint32_t st = sbase + (uint32_t)s * FST;

        // ---- S = Q K^T (3-product split) ----
        #pragma unroll
        for (int nb = 0; nb < 16; nb++)
            #pragma unroll
            for (int q = 0; q < 4; q++) S[nb][q] = 0.f;

        #pragma unroll
        for (int dks = 0; dks < 4; dks++) {
            uint32_t qhi[4], qlo[4];
            uint32_t qoff = SWZ128((uint32_t)((wrow + a_row) * 128 + dks * 32 + a_ch));
            LDSM_X4(qhi, sbase + FQ_OFF + qoff);
            LDSM_X4(qlo, sbase + FQ_OFF + 16384 + qoff);
            #pragma unroll
            for (int nbp = 0; nbp < 8; nbp++) {
                uint32_t khi[4], klo[4];
                uint32_t koff = SWZ128((uint32_t)((nbp * 16 + b_row) * 128 + dks * 32 + b_ch));
                LDSM_X4(khi, st + F_KHI + koff);
                LDSM_X4(klo, st + F_KLO + koff);
                #pragma unroll
                for (int jj = 0; jj < 2; jj++) {
                    uint32_t* bh = &khi[jj * 2];
                    uint32_t* bl = &klo[jj * 2];
                    float* sc = S[nbp * 2 + jj];
                    MMA16816(sc, qhi, bh);
                    MMA16816(sc, qhi, bl);
                    MMA16816(sc, qlo, bh);
                }
            }
        }

        // ---- online softmax (base-2 domain) ----
        #pragma unroll
        for (int nb = 0; nb < 16; nb++)
            #pragma unroll
            for (int q = 0; q < 4; q++) S[nb][q] *= SC2;

        float mxA = -1e30f, mxB = -1e30f;
        #pragma unroll
        for (int nb = 0; nb < 16; nb++) {
            mxA = fmaxf(mxA, fmaxf(S[nb][0], S[nb][1]));
            mxB = fmaxf(mxB, fmaxf(S[nb][2], S[nb][3]));
        }
        #pragma unroll
        for (int d = 1; d <= 2; d <<= 1) {
            mxA = fmaxf(mxA, __shfl_xor_sync(0xffffffffu, mxA, d));
            mxB = fmaxf(mxB, __shfl_xor_sync(0xffffffffu, mxB, d));
        }
        float mAn = fmaxf(mA, mxA), mBn = fmaxf(mB, mxB);
        float fA = ex2f(mA - mAn),  fB = ex2f(mB - mBn);
        float sA = 0.f, sB = 0.f;
        #pragma unroll
        for (int nb = 0; nb < 16; nb++) {
            float p0 = ex2f(S[nb][0] - mAn), p1 = ex2f(S[nb][1] - mAn);
            float p2 = ex2f(S[nb][2] - mBn), p3 = ex2f(S[nb][3] - mBn);
            S[nb][0] = p0; S[nb][1] = p1; S[nb][2] = p2; S[nb][3] = p3;
            sA += p0 + p1; sB += p2 + p3;
        }
        #pragma unroll
        for (int d = 1; d <= 2; d <<= 1) {
            sA += __shfl_xor_sync(0xffffffffu, sA, d);
            sB += __shfl_xor_sync(0xffffffffu, sB, d);
        }
        lA = lA * fA + sA;  lB = lB * fB + sB;
        mA = mAn;           mB = mBn;
        #pragma unroll
        for (int j = 0; j < 8; j++) {
            O[j][0] *= fA; O[j][1] *= fA; O[j][2] *= fB; O[j][3] *= fB;
        }

        // ---- O += P V (3-product split; P from registers) ----
        #pragma unroll
        for (int ks = 0; ks < 8; ks++) {
            uint32_t ph[4], pl[4];
            #pragma unroll
            for (int u = 0; u < 4; u++) {
                const float* sv = S[ks * 2 + (u >> 1)];
                float x0 = sv[(u & 1) * 2], x1 = sv[(u & 1) * 2 + 1];
                __nv_bfloat162 h2 = __floats2bfloat162_rn(x0, x1);
                ph[u] = *(uint32_t*)&h2;
                pl[u] = pack_bf2(x0 - __bfloat162float(h2.x), x1 - __bfloat162float(h2.y));
            }
            #pragma unroll
            for (int dg = 0; dg < 4; dg++) {
                uint32_t vh[4], vl[4];
                uint32_t voff = SWZ128((uint32_t)((ks * 16 + a_row) * 128 + dg * 32 + a_ch));
                LDSM_X4T(vh, st + F_VHI + voff);
                LDSM_X4T(vl, st + F_VLO + voff);
                #pragma unroll
                for (int jj = 0; jj < 2; jj++) {
                    uint32_t* bh = &vh[jj * 2];
                    uint32_t* bl = &vl[jj * 2];
                    float* oc = O[dg * 2 + jj];
                    MMA16816(oc, ph, bh);
                    MMA16816(oc, ph, bl);
                    MMA16816(oc, pl, bh);
                }
            }
        }
        __syncthreads();
    }

    // ---- epilogue: normalize, split to bf16 hi/lo, store ----
    float invA = 1.f / lA, invB = 1.f / lB;
    int rA = bS + q0 + wrow + (lane >> 2);
    int rB = rA + 8;
    #pragma unroll
    for (int j = 0; j < 8; j++) {
        int d0 = j * 8 + (lane & 3) * 2;
        float a0 = O[j][0] * invA, a1 = O[j][1] * invA;
        float b0 = O[j][2] * invB, b1 = O[j][3] * invB;
        __nv_bfloat162 hA = __floats2bfloat162_rn(a0, a1);
        __nv_bfloat162 hB = __floats2bfloat162_rn(b0, b1);
        size_t iA = ((size_t)rA * DIM + hHD + d0) >> 1;
        size_t iB = ((size_t)rB * DIM + hHD + d0) >> 1;
        ((uint32_t*)Ahi)[iA] = *(uint32_t*)&hA;
        ((uint32_t*)Ahi)[iB] = *(uint32_t*)&hB;
        ((uint32_t*)Alo)[iA] = pack_bf2(a0 - __bfloat162float(hA.x), a1 - __bfloat162float(hA.y));
        ((uint32_t*)Alo)[iB] = pack_bf2(b0 - __bfloat162float(hB.x), b1 - __bfloat162float(hB.y));
    }
}

// ---------------------------------------------------------------------------
extern "C" void kernel_launch(void* const* d_in, const int* in_sizes, int n_in,
                              void* d_out, int out_size)
{
    const float* x     = (const float*)d_in[0];
    const float* Wqkv  = (const float*)d_in[1];
    const float* Wproj = (const float*)d_in[2];
    float* out = (float*)d_out;

    __nv_bfloat16 *xhi, *xlo, *qh, *ql, *ahi, *alo, *wqhi, *wqlo, *wphi, *wplo;
    cudaGetSymbolAddress((void**)&xhi,  g_xhi);
    cudaGetSymbolAddress((void**)&xlo,  g_xlo);
    cudaGetSymbolAddress((void**)&qh,   g_qh);
    cudaGetSymbolAddress((void**)&ql,   g_ql);
    cudaGetSymbolAddress((void**)&ahi,  g_ahi);
    cudaGetSymbolAddress((void**)&alo,  g_alo);
    cudaGetSymbolAddress((void**)&wqhi, g_wqhi);
    cudaGetSymbolAddress((void**)&wqlo, g_wqlo);
    cudaGetSymbolAddress((void**)&wphi, g_wphi);
    cudaGetSymbolAddress((void**)&wplo, g_wplo);

    const int M = BATCH * SEQ;          // 4096

    cudaFuncSetAttribute(gemm_mma<true>,  cudaFuncAttributeMaxDynamicSharedMemorySize, GSMEM_TOTAL);
    cudaFuncSetAttribute(gemm_mma<false>, cudaFuncAttributeMaxDynamicSharedMemorySize, GSMEM_TOTAL);
    cudaFuncSetAttribute(flash_mma,       cudaFuncAttributeMaxDynamicSharedMemorySize, FSMEM_TOTAL);

    // 0) splits
    split_kernel<<<(M * DIM / 4 + 255) / 256, 256>>>(x, xhi, xlo, M * DIM / 4);
    {
        dim3 g1(3 * DIM / 32, DIM / 32);
        transpose_split<<<g1, 256>>>(Wqkv, wqhi, wqlo, DIM, 3 * DIM);
        dim3 g2(DIM / 32, DIM / 32);
        transpose_split<<<g2, 256>>>(Wproj, wphi, wplo, DIM, DIM);
    }

    // 1) qkv = x @ Wqkv -> bf16 hi/lo directly
    {
        dim3 grid(3 * DIM / 128, M / 128);
        gemm_mma<true><<<grid, 256, GSMEM_TOTAL>>>(xhi, xlo, wqhi, wqlo,
                                                   nullptr, qh, ql, M, 3 * DIM, DIM);
    }

    // 2) flash attention (HMMA) -> bf16 hi/lo directly
    {
        dim3 grid(SEQ / 128, NHEAD, BATCH);
        flash_mma<<<grid, 256, FSMEM_TOTAL>>>(qh, ql, ahi, alo);
    }

    // 3) out = attn @ Wproj (fp32 out)
    {
        dim3 grid(DIM / 128, M / 128);
        gemm_mma<false><<<grid, 256, GSMEM_TOTAL>>>(ahi, alo, wphi, wplo,
                                                    out, nullptr, nullptr, M, DIM, DIM);
    }
}

// round 6
// speedup vs baseline: 3.9475x; 1.0735x over previous
#include <cuda_runtime.h>
#include <cuda_bf16.h>
#include <cstdint>
#include <cstddef>

#define BATCH 2
#define SEQ   2048
#define DIM   1024
#define NHEAD 16
#define HD    64
// SCALE * log2(e): logits kept in base-2 domain
#define SC2   0.18033688011112042f

// ---------------------------------------------------------------------------
// Scratch (allocation-free rule: __device__ globals)
// ---------------------------------------------------------------------------
__device__ __nv_bfloat16 g_xhi[(size_t)BATCH * SEQ * DIM];
__device__ __nv_bfloat16 g_xlo[(size_t)BATCH * SEQ * DIM];
__device__ __nv_bfloat16 g_qh [(size_t)BATCH * SEQ * 3 * DIM];   // qkv hi
__device__ __nv_bfloat16 g_ql [(size_t)BATCH * SEQ * 3 * DIM];   // qkv lo
__device__ __nv_bfloat16 g_ahi[(size_t)BATCH * SEQ * DIM];       // attn hi
__device__ __nv_bfloat16 g_alo[(size_t)BATCH * SEQ * DIM];       // attn lo
__device__ __nv_bfloat16 g_wqhi[(size_t)3 * DIM * DIM];          // [3072,1024] K-major
__device__ __nv_bfloat16 g_wqlo[(size_t)3 * DIM * DIM];
__device__ __nv_bfloat16 g_wphi[(size_t)DIM * DIM];
__device__ __nv_bfloat16 g_wplo[(size_t)DIM * DIM];

// ---------------------------------------------------------------------------
// Portable PTX helpers
// ---------------------------------------------------------------------------
__device__ __forceinline__ uint32_t smem_u32(const void* p) {
    uint32_t a;
    asm("{ .reg .u64 t; cvta.to.shared.u64 t, %1; cvt.u32.u64 %0, t; }" : "=r"(a) : "l"(p));
    return a;
}
#define CPA16(dst, src) \
    asm volatile("cp.async.cg.shared.global [%0], [%1], 16;" :: "r"(dst), "l"(src) : "memory")
#define CP_COMMIT() asm volatile("cp.async.commit_group;" ::: "memory")
#define CP_WAIT0()  asm volatile("cp.async.wait_group 0;" ::: "memory")
#define CP_WAIT1()  asm volatile("cp.async.wait_group 1;" ::: "memory")

#define LDSM_X4(r, addr) \
    asm volatile("ldmatrix.sync.aligned.m8n8.x4.shared.b16 {%0,%1,%2,%3}, [%4];" \
        : "=r"((r)[0]), "=r"((r)[1]), "=r"((r)[2]), "=r"((r)[3]) : "r"(addr))
#define LDSM_X4T(r, addr) \
    asm volatile("ldmatrix.sync.aligned.m8n8.x4.trans.shared.b16 {%0,%1,%2,%3}, [%4];" \
        : "=r"((r)[0]), "=r"((r)[1]), "=r"((r)[2]), "=r"((r)[3]) : "r"(addr))

#define MMA16816(c, a, b) \
    asm volatile("mma.sync.aligned.m16n8k16.row.col.f32.bf16.bf16.f32 " \
        "{%0,%1,%2,%3}, {%4,%5,%6,%7}, {%8,%9}, {%0,%1,%2,%3};" \
        : "+f"((c)[0]), "+f"((c)[1]), "+f"((c)[2]), "+f"((c)[3]) \
        : "r"((a)[0]), "r"((a)[1]), "r"((a)[2]), "r"((a)[3]), "r"((b)[0]), "r"((b)[1]))

#define SWZ64(off)  ((off) ^ (((off) >> 3) & 0x30))
#define SWZ128(off) ((off) ^ (((off) >> 3) & 0x70))

__device__ __forceinline__ float ex2f(float x) {
    float y; asm("ex2.approx.ftz.f32 %0, %1;" : "=f"(y) : "f"(x)); return y;
}
__device__ __forceinline__ uint32_t pack_bf2(float lo, float hi) {
    __nv_bfloat162 h = __floats2bfloat162_rn(lo, hi);
    return *(uint32_t*)&h;
}

// ---------------------------------------------------------------------------
// Preprocessing
// ---------------------------------------------------------------------------
__global__ __launch_bounds__(256) void split_kernel(
    const float* __restrict__ X, __nv_bfloat16* __restrict__ hi,
    __nv_bfloat16* __restrict__ lo, int n4)
{
    int i = blockIdx.x * blockDim.x + threadIdx.x;
    if (i >= n4) return;
    float4 v = ((const float4*)X)[i];
    __nv_bfloat16 h[4], l[4];
    float f[4] = {v.x, v.y, v.z, v.w};
    #pragma unroll
    for (int j = 0; j < 4; j++) {
        h[j] = __float2bfloat16(f[j]);
        l[j] = __float2bfloat16(f[j] - __bfloat162float(h[j]));
    }
    ((uint2*)hi)[i] = *(uint2*)h;
    ((uint2*)lo)[i] = *(uint2*)l;
}

__global__ __launch_bounds__(256) void transpose_split(
    const float* __restrict__ W, __nv_bfloat16* __restrict__ Thi,
    __nv_bfloat16* __restrict__ Tlo, int K, int N)
{
    __shared__ float tile[32][33];
    int tx = threadIdx.x & 31, ty = threadIdx.x >> 5;
    int k0 = blockIdx.y * 32, n0 = blockIdx.x * 32;
    #pragma unroll
    for (int i = 0; i < 32; i += 8)
        tile[ty + i][tx] = W[(size_t)(k0 + ty + i) * N + n0 + tx];
    __syncthreads();
    #pragma unroll
    for (int i = 0; i < 32; i += 8) {
        float v = tile[tx][ty + i];
        __nv_bfloat16 h = __float2bfloat16(v);
        __nv_bfloat16 l = __float2bfloat16(v - __bfloat162float(h));
        size_t o = (size_t)(n0 + ty + i) * K + k0 + tx;
        Thi[o] = h; Tlo[o] = l;
    }
}

// ---------------------------------------------------------------------------
// HMMA bf16-split GEMM: C = A[M,K] @ T[N,K]^T, fp32 or bf16-hi/lo output
// CTA 128x128, BK=32, double buffer, 8 warps (4m x 2n), 2 CTAs/SM target.
// ---------------------------------------------------------------------------
#define GST 32768
#define GSMEM_TOTAL (2 * GST)

#define LOAD_STAGE(sidx, kc) do {                                              \
    uint32_t sb = sbase + (uint32_t)(sidx) * GST;                              \
    _Pragma("unroll")                                                          \
    for (int t_ = 0; t_ < 2; ++t_) {                                           \
        int v_ = tid + t_ * 256;                                               \
        int row_ = v_ >> 2, cb_ = v_ & 3;                                      \
        uint32_t sw_ = SWZ64((uint32_t)(row_ * 64 + cb_ * 16));                \
        size_t gA_ = (size_t)(rowBase + row_) * K + (kc) + cb_ * 8;            \
        size_t gB_ = (size_t)(colBase + row_) * K + (kc) + cb_ * 8;            \
        CPA16(sb + sw_,         (const char*)(Ahi + gA_));                     \
        CPA16(sb + 8192  + sw_, (const char*)(Alo + gA_));                     \
        CPA16(sb + 16384 + sw_, (const char*)(Bhi + gB_));                     \
        CPA16(sb + 24576 + sw_, (const char*)(Blo + gB_));                     \
    }                                                                          \
} while (0)

template <bool SPLIT>
__global__ __launch_bounds__(256, 2) void gemm_mma(
    const __nv_bfloat16* __restrict__ Ahi, const __nv_bfloat16* __restrict__ Alo,
    const __nv_bfloat16* __restrict__ Bhi, const __nv_bfloat16* __restrict__ Blo,
    float* __restrict__ C, __nv_bfloat16* __restrict__ Chi,
    __nv_bfloat16* __restrict__ Clo, int M, int N, int K)
{
    extern __shared__ char smem[];
    const uint32_t sbase = smem_u32(smem);
    const int tid  = threadIdx.x;
    const int lane = tid & 31;
    const int wid  = tid >> 5;
    const int wm = (wid & 3) * 32;
    const int wn = (wid >> 2) * 64;
    const int rowBase = blockIdx.y * 128;
    const int colBase = blockIdx.x * 128;

    const int mi = lane >> 3;
    const uint32_t a_off = (uint32_t)((((mi & 1) * 8 + (lane & 7)) * 64) + (mi >> 1) * 16);
    const uint32_t b_off = (uint32_t)((((mi >> 1) * 8 + (lane & 7)) * 64) + (mi & 1) * 16);

    float acc[2][8][4];
    #pragma unroll
    for (int i = 0; i < 2; i++)
        #pragma unroll
        for (int j = 0; j < 8; j++)
            #pragma unroll
            for (int q = 0; q < 4; q++) acc[i][j][q] = 0.f;

    const int nk = K / 32;
    LOAD_STAGE(0, 0);
    CP_COMMIT();

    for (int c = 0; c < nk; ++c) {
        const int s = c & 1;
        if (c + 1 < nk) { LOAD_STAGE((c + 1) & 1, (c + 1) * 32); CP_COMMIT(); CP_WAIT1(); }
        else           { CP_WAIT0(); }
        __syncthreads();

        const uint32_t st = sbase + (uint32_t)s * GST;
        #pragma unroll
        for (int kb = 0; kb < 64; kb += 32) {
            uint32_t ahi[2][4], alo[2][4];
            #pragma unroll
            for (int i = 0; i < 2; i++) {
                uint32_t off = (uint32_t)((wm + i * 16) * 64 + kb) + a_off;
                LDSM_X4(ahi[i], st + SWZ64(off));
                LDSM_X4(alo[i], st + 8192 + SWZ64(off));
            }
            // stream B fragments per 16-col block (keeps live regs < 128)
            #pragma unroll
            for (int jp = 0; jp < 4; jp++) {
                uint32_t bhi[4], blo[4];
                uint32_t off = (uint32_t)((wn + jp * 16) * 64 + kb) + b_off;
                LDSM_X4(bhi, st + 16384 + SWZ64(off));
                LDSM_X4(blo, st + 24576 + SWZ64(off));
                #pragma unroll
                for (int i = 0; i < 2; i++)
                    #pragma unroll
                    for (int jj = 0; jj < 2; jj++) {
                        uint32_t* bh = &bhi[jj * 2];
                        uint32_t* bl = &blo[jj * 2];
                        float* ac = acc[i][jp * 2 + jj];
                        MMA16816(ac, ahi[i], bh);
                        MMA16816(ac, ahi[i], bl);
                        MMA16816(ac, alo[i], bh);
                    }
            }
        }
        __syncthreads();
    }

    #pragma unroll
    for (int i = 0; i < 2; i++) {
        #pragma unroll
        for (int j = 0; j < 8; j++) {
            int r0 = rowBase + wm + i * 16 + (lane >> 2);
            int c0 = colBase + wn + j * 8 + (lane & 3) * 2;
            if (SPLIT) {
                #pragma unroll
                for (int hh = 0; hh < 2; hh++) {
                    float v0 = acc[i][j][hh * 2], v1 = acc[i][j][hh * 2 + 1];
                    __nv_bfloat162 h2 = __floats2bfloat162_rn(v0, v1);
                    float l0 = v0 - __bfloat162float(h2.x);
                    float l1 = v1 - __bfloat162float(h2.y);
                    size_t idx = ((size_t)(r0 + hh * 8) * N + c0) >> 1;
                    ((uint32_t*)Chi)[idx] = *(uint32_t*)&h2;
                    ((uint32_t*)Clo)[idx] = pack_bf2(l0, l1);
                }
            } else {
                *(float2*)&C[(size_t)r0 * N + c0]       = make_float2(acc[i][j][0], acc[i][j][1]);
                *(float2*)&C[(size_t)(r0 + 8) * N + c0] = make_float2(acc[i][j][2], acc[i][j][3]);
            }
        }
    }
}

// ---------------------------------------------------------------------------
// Flash attention, HMMA. CTA = 128 q rows of one (b,h); 8 warps x 16 rows.
// Bc=64: stage = [Khi|Klo|Vhi|Vlo] 8KB each = 32KB; 2 stages + Q 32KB = 96KB.
// Target 2 CTAs/SM.
// ---------------------------------------------------------------------------
#define FST     32768
#define F_KHI   0
#define F_KLO   8192
#define F_VHI   16384
#define F_VLO   24576
#define FQ_OFF  (2 * FST)
#define FSMEM_TOTAL (2 * FST + 32768)

#define FLOAD_KV(sidx, c0b) do {                                               \
    uint32_t sb = sbase + (uint32_t)(sidx) * FST;                              \
    _Pragma("unroll")                                                          \
    for (int t_ = 0; t_ < 2; ++t_) {                                           \
        int v_ = tid + t_ * 256;                                               \
        int row_ = v_ >> 3, ch_ = v_ & 7;                                      \
        uint32_t sw_ = SWZ128((uint32_t)(row_ * 128 + ch_ * 16));              \
        size_t base_ = ((size_t)(bS + (c0b) + row_) * 3) * DIM + hHD + ch_ * 8;\
        CPA16(sb + F_KHI + sw_, (const char*)(qh + base_ + DIM));              \
        CPA16(sb + F_KLO + sw_, (const char*)(ql + base_ + DIM));              \
        CPA16(sb + F_VHI + sw_, (const char*)(qh + base_ + 2 * DIM));          \
        CPA16(sb + F_VLO + sw_, (const char*)(ql + base_ + 2 * DIM));          \
    }                                                                          \
} while (0)

__global__ __launch_bounds__(256, 2) void flash_mma(
    const __nv_bfloat16* __restrict__ qh, const __nv_bfloat16* __restrict__ ql,
    __nv_bfloat16* __restrict__ Ahi, __nv_bfloat16* __restrict__ Alo)
{
    extern __shared__ char smem[];
    const uint32_t sbase = smem_u32(smem);
    const int tid  = threadIdx.x;
    const int lane = tid & 31;
    const int wid  = tid >> 5;
    const int wrow = wid * 16;
    const int h  = blockIdx.y;
    const int b  = blockIdx.z;
    const int q0 = blockIdx.x * 128;
    const int bS  = b * SEQ;
    const int hHD = h * HD;

    const int mi = lane >> 3;
    const uint32_t a_row = (mi & 1) * 8 + (lane & 7);
    const uint32_t a_ch  = (mi >> 1) * 16;
    const uint32_t b_row = (mi >> 1) * 8 + (lane & 7);
    const uint32_t b_ch  = (mi & 1) * 16;

    // Q tile (once) + first KV stage
    {
        #pragma unroll
        for (int t_ = 0; t_ < 4; ++t_) {
            int v_ = tid + t_ * 256;
            int row_ = v_ >> 3, ch_ = v_ & 7;
            uint32_t sw_ = SWZ128((uint32_t)(row_ * 128 + ch_ * 16));
            size_t base_ = ((size_t)(bS + q0 + row_) * 3) * DIM + hHD + ch_ * 8;
            CPA16(sbase + FQ_OFF + sw_,         (const char*)(qh + base_));
            CPA16(sbase + FQ_OFF + 16384 + sw_, (const char*)(ql + base_));
        }
        FLOAD_KV(0, 0);
        CP_COMMIT();
    }

    float S[8][4];
    float O[8][4];
    #pragma unroll
    for (int j = 0; j < 8; j++)
        #pragma unroll
        for (int q = 0; q < 4; q++) O[j][q] = 0.f;
    float mA = -1e30f, mB = -1e30f, lA = 0.f, lB = 0.f;

    const int ntiles = SEQ / 64;   // 32

    for (int tI = 0; tI < ntiles; ++tI) {
        const int s = tI & 1;
        if (tI + 1 < ntiles) { FLOAD_KV((tI + 1) & 1, (tI + 1) * 64); CP_COMMIT(); CP_WAIT1(); }
        else                 { CP_WAIT0(); }
        __syncthreads();

        const uint32_t st = sbase + (uint32_t)s * FST;

        // ---- S = Q K^T (3-product split) ----
        #pragma unroll
        for (int nb = 0; nb < 8; nb++)
            #pragma unroll
            for (int q = 0; q < 4; q++) S[nb][q] = 0.f;

        #pragma unroll
        for (int dks = 0; dks < 4; dks++) {
            uint32_t qhi[4], qlo[4];
            uint32_t qoff = SWZ128((uint32_t)((wrow + a_row) * 128 + dks * 32 + a_ch));
            LDSM_X4(qhi, sbase + FQ_OFF + qoff);
            LDSM_X4(qlo, sbase + FQ_OFF + 16384 + qoff);
            #pragma unroll
            for (int nbp = 0; nbp < 4; nbp++) {
                uint32_t khi[4], klo[4];
                uint32_t koff = SWZ128((uint32_t)((nbp * 16 + b_row) * 128 + dks * 32 + b_ch));
                LDSM_X4(khi, st + F_KHI + koff);
                LDSM_X4(klo, st + F_KLO + koff);
                #pragma unroll
                for (int jj = 0; jj < 2; jj++) {
                    uint32_t* bh = &khi[jj * 2];
                    uint32_t* bl = &klo[jj * 2];
                    float* sc = S[nbp * 2 + jj];
                    MMA16816(sc, qhi, bh);
                    MMA16816(sc, qhi, bl);
                    MMA16816(sc, qlo, bh);
                }
            }
        }

        // ---- online softmax (base-2 domain) ----
        #pragma unroll
        for (int nb = 0; nb < 8; nb++)
            #pragma unroll
            for (int q = 0; q < 4; q++) S[nb][q] *= SC2;

        float mxA = -1e30f, mxB = -1e30f;
        #pragma unroll
        for (int nb = 0; nb < 8; nb++) {
            mxA = fmaxf(mxA, fmaxf(S[nb][0], S[nb][1]));
            mxB = fmaxf(mxB, fmaxf(S[nb][2], S[nb][3]));
        }
        #pragma unroll
        for (int d = 1; d <= 2; d <<= 1) {
            mxA = fmaxf(mxA, __shfl_xor_sync(0xffffffffu, mxA, d));
            mxB = fmaxf(mxB, __shfl_xor_sync(0xffffffffu, mxB, d));
        }
        float mAn = fmaxf(mA, mxA), mBn = fmaxf(mB, mxB);
        float fA = ex2f(mA - mAn),  fB = ex2f(mB - mBn);
        float sA = 0.f, sB = 0.f;
        #pragma unroll
        for (int nb = 0; nb < 8; nb++) {
            float p0 = ex2f(S[nb][0] - mAn), p1 = ex2f(S[nb][1] - mAn);
            float p2 = ex2f(S[nb][2] - mBn), p3 = ex2f(S[nb][3] - mBn);
            S[nb][0] = p0; S[nb][1] = p1; S[nb][2] = p2; S[nb][3] = p3;
            sA += p0 + p1; sB += p2 + p3;
        }
        #pragma unroll
        for (int d = 1; d <= 2; d <<= 1) {
            sA += __shfl_xor_sync(0xffffffffu, sA, d);
            sB += __shfl_xor_sync(0xffffffffu, sB, d);
        }
        lA = lA * fA + sA;  lB = lB * fB + sB;
        mA = mAn;           mB = mBn;
        #pragma unroll
        for (int j = 0; j < 8; j++) {
            O[j][0] *= fA; O[j][1] *= fA; O[j][2] *= fB; O[j][3] *= fB;
        }

        // ---- O += P V (3-product split; P from registers) ----
        #pragma unroll
        for (int ks = 0; ks < 4; ks++) {
            uint32_t ph[4], pl[4];
            #pragma unroll
            for (int u = 0; u < 4; u++) {
                const float* sv = S[ks * 2 + (u >> 1)];
                float x0 = sv[(u & 1) * 2], x1 = sv[(u & 1) * 2 + 1];
                __nv_bfloat162 h2 = __floats2bfloat162_rn(x0, x1);
                ph[u] = *(uint32_t*)&h2;
                pl[u] = pack_bf2(x0 - __bfloat162float(h2.x), x1 - __bfloat162float(h2.y));
            }
            #pragma unroll
            for (int dg = 0; dg < 4; dg++) {
                uint32_t vh[4], vl[4];
                uint32_t voff = SWZ128((uint32_t)((ks * 16 + a_row) * 128 + dg * 32 + a_ch));
                LDSM_X4T(vh, st + F_VHI + voff);
                LDSM_X4T(vl, st + F_VLO + voff);
                #pragma unroll
                for (int jj = 0; jj < 2; jj++) {
                    uint32_t* bh = &vh[jj * 2];
                    uint32_t* bl = &vl[jj * 2];
                    float* oc = O[dg * 2 + jj];
                    MMA16816(oc, ph, bh);
                    MMA16816(oc, ph, bl);
                    MMA16816(oc, pl, bh);
                }
            }
        }
        __syncthreads();
    }

    // ---- epilogue: normalize, split to bf16 hi/lo, store ----
    float invA = 1.f / lA, invB = 1.f / lB;
    int rA = bS + q0 + wrow + (lane >> 2);
    int rB = rA + 8;
    #pragma unroll
    for (int j = 0; j < 8; j++) {
        int d0 = j * 8 + (lane & 3) * 2;
        float a0 = O[j][0] * invA, a1 = O[j][1] * invA;
        float b0 = O[j][2] * invB, b1 = O[j][3] * invB;
        __nv_bfloat162 hA = __floats2bfloat162_rn(a0, a1);
        __nv_bfloat162 hB = __floats2bfloat162_rn(b0, b1);
        size_t iA = ((size_t)rA * DIM + hHD + d0) >> 1;
        size_t iB = ((size_t)rB * DIM + hHD + d0) >> 1;
        ((uint32_t*)Ahi)[iA] = *(uint32_t*)&hA;
        ((uint32_t*)Ahi)[iB] = *(uint32_t*)&hB;
        ((uint32_t*)Alo)[iA] = pack_bf2(a0 - __bfloat162float(hA.x), a1 - __bfloat162float(hA.y));
        ((uint32_t*)Alo)[iB] = pack_bf2(b0 - __bfloat162float(hB.x), b1 - __bfloat162float(hB.y));
    }
}

// ---------------------------------------------------------------------------
extern "C" void kernel_launch(void* const* d_in, const int* in_sizes, int n_in,
                              void* d_out, int out_size)
{
    const float* x     = (const float*)d_in[0];
    const float* Wqkv  = (const float*)d_in[1];
    const float* Wproj = (const float*)d_in[2];
    float* out = (float*)d_out;

    __nv_bfloat16 *xhi, *xlo, *qh, *ql, *ahi, *alo, *wqhi, *wqlo, *wphi, *wplo;
    cudaGetSymbolAddress((void**)&xhi,  g_xhi);
    cudaGetSymbolAddress((void**)&xlo,  g_xlo);
    cudaGetSymbolAddress((void**)&qh,   g_qh);
    cudaGetSymbolAddress((void**)&ql,   g_ql);
    cudaGetSymbolAddress((void**)&ahi,  g_ahi);
    cudaGetSymbolAddress((void**)&alo,  g_alo);
    cudaGetSymbolAddress((void**)&wqhi, g_wqhi);
    cudaGetSymbolAddress((void**)&wqlo, g_wqlo);
    cudaGetSymbolAddress((void**)&wphi, g_wphi);
    cudaGetSymbolAddress((void**)&wplo, g_wplo);

    const int M = BATCH * SEQ;          // 4096

    cudaFuncSetAttribute(gemm_mma<true>,  cudaFuncAttributeMaxDynamicSharedMemorySize, GSMEM_TOTAL);
    cudaFuncSetAttribute(gemm_mma<false>, cudaFuncAttributeMaxDynamicSharedMemorySize, GSMEM_TOTAL);
    cudaFuncSetAttribute(flash_mma,       cudaFuncAttributeMaxDynamicSharedMemorySize, FSMEM_TOTAL);

    // 0) splits
    split_kernel<<<(M * DIM / 4 + 255) / 256, 256>>>(x, xhi, xlo, M * DIM / 4);
    {
        dim3 g1(3 * DIM / 32, DIM / 32);
        transpose_split<<<g1, 256>>>(Wqkv, wqhi, wqlo, DIM, 3 * DIM);
        dim3 g2(DIM / 32, DIM / 32);
        transpose_split<<<g2, 256>>>(Wproj, wphi, wplo, DIM, DIM);
    }

    // 1) qkv = x @ Wqkv -> bf16 hi/lo directly
    {
        dim3 grid(3 * DIM / 128, M / 128);
        gemm_mma<true><<<grid, 256, GSMEM_TOTAL>>>(xhi, xlo, wqhi, wqlo,
                                                   nullptr, qh, ql, M, 3 * DIM, DIM);
    }

    // 2) flash attention (HMMA) -> bf16 hi/lo directly
    {
        dim3 grid(SEQ / 128, NHEAD, BATCH);
        flash_mma<<<grid, 256, FSMEM_TOTAL>>>(qh, ql, ahi, alo);
    }

    // 3) out = attn @ Wproj (fp32 out)
    {
        dim3 grid(DIM / 128, M / 128);
        gemm_mma<false><<<grid, 256, GSMEM_TOTAL>>>(ahi, alo, wphi, wplo,
                                                    out, nullptr, nullptr, M, DIM, DIM);
    }
}

// round 7
// speedup vs baseline: 4.0327x; 1.0216x over previous
#include <cuda_runtime.h>
#include <cuda_bf16.h>
#include <cstdint>
#include <cstddef>

#define BATCH 2
#define SEQ   2048
#define DIM   1024
#define NHEAD 16
#define HD    64
// SCALE * log2(e): logits kept in base-2 domain
#define SC2   0.18033688011112042f

// ---------------------------------------------------------------------------
// Scratch (allocation-free rule: __device__ globals)
// ---------------------------------------------------------------------------
__device__ __nv_bfloat16 g_xhi[(size_t)BATCH * SEQ * DIM];
__device__ __nv_bfloat16 g_xlo[(size_t)BATCH * SEQ * DIM];
__device__ __nv_bfloat16 g_qh [(size_t)BATCH * SEQ * 3 * DIM];   // qkv hi
__device__ __nv_bfloat16 g_ql [(size_t)BATCH * SEQ * 3 * DIM];   // qkv lo
__device__ __nv_bfloat16 g_ahi[(size_t)BATCH * SEQ * DIM];       // attn hi
__device__ __nv_bfloat16 g_alo[(size_t)BATCH * SEQ * DIM];       // attn lo
__device__ __nv_bfloat16 g_wqhi[(size_t)3 * DIM * DIM];          // [3072,1024] K-major
__device__ __nv_bfloat16 g_wqlo[(size_t)3 * DIM * DIM];
__device__ __nv_bfloat16 g_wphi[(size_t)DIM * DIM];
__device__ __nv_bfloat16 g_wplo[(size_t)DIM * DIM];

// ---------------------------------------------------------------------------
// Portable PTX helpers
// ---------------------------------------------------------------------------
__device__ __forceinline__ uint32_t smem_u32(const void* p) {
    uint32_t a;
    asm("{ .reg .u64 t; cvta.to.shared.u64 t, %1; cvt.u32.u64 %0, t; }" : "=r"(a) : "l"(p));
    return a;
}
#define CPA16(dst, src) \
    asm volatile("cp.async.cg.shared.global [%0], [%1], 16;" :: "r"(dst), "l"(src) : "memory")
#define CP_COMMIT() asm volatile("cp.async.commit_group;" ::: "memory")
#define CP_WAIT0()  asm volatile("cp.async.wait_group 0;" ::: "memory")
#define CP_WAIT1()  asm volatile("cp.async.wait_group 1;" ::: "memory")

#define LDSM_X4(r, addr) \
    asm volatile("ldmatrix.sync.aligned.m8n8.x4.shared.b16 {%0,%1,%2,%3}, [%4];" \
        : "=r"((r)[0]), "=r"((r)[1]), "=r"((r)[2]), "=r"((r)[3]) : "r"(addr))
#define LDSM_X4T(r, addr) \
    asm volatile("ldmatrix.sync.aligned.m8n8.x4.trans.shared.b16 {%0,%1,%2,%3}, [%4];" \
        : "=r"((r)[0]), "=r"((r)[1]), "=r"((r)[2]), "=r"((r)[3]) : "r"(addr))

#define MMA16816(c, a, b) \
    asm volatile("mma.sync.aligned.m16n8k16.row.col.f32.bf16.bf16.f32 " \
        "{%0,%1,%2,%3}, {%4,%5,%6,%7}, {%8,%9}, {%0,%1,%2,%3};" \
        : "+f"((c)[0]), "+f"((c)[1]), "+f"((c)[2]), "+f"((c)[3]) \
        : "r"((a)[0]), "r"((a)[1]), "r"((a)[2]), "r"((a)[3]), "r"((b)[0]), "r"((b)[1]))

#define SWZ64(off)  ((off) ^ (((off) >> 3) & 0x30))
#define SWZ128(off) ((off) ^ (((off) >> 3) & 0x70))

__device__ __forceinline__ float ex2f(float x) {
    float y; asm("ex2.approx.ftz.f32 %0, %1;" : "=f"(y) : "f"(x)); return y;
}
__device__ __forceinline__ uint32_t pack_bf2(float lo, float hi) {
    __nv_bfloat162 h = __floats2bfloat162_rn(lo, hi);
    return *(uint32_t*)&h;
}

// ---------------------------------------------------------------------------
// Preprocessing
// ---------------------------------------------------------------------------
__global__ __launch_bounds__(256) void split_kernel(
    const float* __restrict__ X, __nv_bfloat16* __restrict__ hi,
    __nv_bfloat16* __restrict__ lo, int n4)
{
    int i = blockIdx.x * blockDim.x + threadIdx.x;
    if (i >= n4) return;
    float4 v = ((const float4*)X)[i];
    __nv_bfloat16 h[4], l[4];
    float f[4] = {v.x, v.y, v.z, v.w};
    #pragma unroll
    for (int j = 0; j < 4; j++) {
        h[j] = __float2bfloat16(f[j]);
        l[j] = __float2bfloat16(f[j] - __bfloat162float(h[j]));
    }
    ((uint2*)hi)[i] = *(uint2*)h;
    ((uint2*)lo)[i] = *(uint2*)l;
}

__global__ __launch_bounds__(256) void transpose_split(
    const float* __restrict__ W, __nv_bfloat16* __restrict__ Thi,
    __nv_bfloat16* __restrict__ Tlo, int K, int N)
{
    __shared__ float tile[32][33];
    int tx = threadIdx.x & 31, ty = threadIdx.x >> 5;
    int k0 = blockIdx.y * 32, n0 = blockIdx.x * 32;
    #pragma unroll
    for (int i = 0; i < 32; i += 8)
        tile[ty + i][tx] = W[(size_t)(k0 + ty + i) * N + n0 + tx];
    __syncthreads();
    #pragma unroll
    for (int i = 0; i < 32; i += 8) {
        float v = tile[tx][ty + i];
        __nv_bfloat16 h = __float2bfloat16(v);
        __nv_bfloat16 l = __float2bfloat16(v - __bfloat162float(h));
        size_t o = (size_t)(n0 + ty + i) * K + k0 + tx;
        Thi[o] = h; Tlo[o] = l;
    }
}

// ---------------------------------------------------------------------------
// HMMA bf16-split GEMM: C = A[M,K] @ T[N,K]^T, fp32 or bf16-hi/lo output
// CTA 128x128, BK=32, 3-stage cp.async, single barrier/iter, 2 CTAs/SM.
// ---------------------------------------------------------------------------
#define GST 32768
#define GSMEM_TOTAL (3 * GST)

#define LOAD_STAGE(sidx, kc) do {                                              \
    uint32_t sb = sbase + (uint32_t)(sidx) * GST;                              \
    _Pragma("unroll")                                                          \
    for (int t_ = 0; t_ < 2; ++t_) {                                           \
        int v_ = tid + t_ * 256;                                               \
        int row_ = v_ >> 2, cb_ = v_ & 3;                                      \
        uint32_t sw_ = SWZ64((uint32_t)(row_ * 64 + cb_ * 16));                \
        size_t gA_ = (size_t)(rowBase + row_) * K + (kc) + cb_ * 8;            \
        size_t gB_ = (size_t)(colBase + row_) * K + (kc) + cb_ * 8;            \
        CPA16(sb + sw_,         (const char*)(Ahi + gA_));                     \
        CPA16(sb + 8192  + sw_, (const char*)(Alo + gA_));                     \
        CPA16(sb + 16384 + sw_, (const char*)(Bhi + gB_));                     \
        CPA16(sb + 24576 + sw_, (const char*)(Blo + gB_));                     \
    }                                                                          \
} while (0)

template <bool SPLIT>
__global__ __launch_bounds__(256, 2) void gemm_mma(
    const __nv_bfloat16* __restrict__ Ahi, const __nv_bfloat16* __restrict__ Alo,
    const __nv_bfloat16* __restrict__ Bhi, const __nv_bfloat16* __restrict__ Blo,
    float* __restrict__ C, __nv_bfloat16* __restrict__ Chi,
    __nv_bfloat16* __restrict__ Clo, int M, int N, int K)
{
    extern __shared__ char smem[];
    const uint32_t sbase = smem_u32(smem);
    const int tid  = threadIdx.x;
    const int lane = tid & 31;
    const int wid  = tid >> 5;
    const int wm = (wid & 3) * 32;
    const int wn = (wid >> 2) * 64;
    const int rowBase = blockIdx.y * 128;
    const int colBase = blockIdx.x * 128;

    const int mi = lane >> 3;
    const uint32_t a_off = (uint32_t)((((mi & 1) * 8 + (lane & 7)) * 64) + (mi >> 1) * 16);
    const uint32_t b_off = (uint32_t)((((mi >> 1) * 8 + (lane & 7)) * 64) + (mi & 1) * 16);

    float acc[2][8][4];
    #pragma unroll
    for (int i = 0; i < 2; i++)
        #pragma unroll
        for (int j = 0; j < 8; j++)
            #pragma unroll
            for (int q = 0; q < 4; q++) acc[i][j][q] = 0.f;

    const int nk = K / 32;                 // 32
    LOAD_STAGE(0, 0);  CP_COMMIT();
    LOAD_STAGE(1, 32); CP_COMMIT();

    int sidx = 0;                          // stage of chunk c (mod 3)
    for (int c = 0; c < nk; ++c) {
        if (c + 1 < nk) { CP_WAIT1(); } else { CP_WAIT0(); }
        __syncthreads();                   // all warps done with compute(c-1)
        if (c + 2 < nk) {
            int ns = sidx + 2; if (ns >= 3) ns -= 3;
            LOAD_STAGE(ns, (c + 2) * 32);
            CP_COMMIT();
        }

        const uint32_t st = sbase + (uint32_t)sidx * GST;
        #pragma unroll
        for (int kb = 0; kb < 64; kb += 32) {
            uint32_t ahi[2][4], alo[2][4];
            #pragma unroll
            for (int i = 0; i < 2; i++) {
                uint32_t off = (uint32_t)((wm + i * 16) * 64 + kb) + a_off;
                LDSM_X4(ahi[i], st + SWZ64(off));
                LDSM_X4(alo[i], st + 8192 + SWZ64(off));
            }
            #pragma unroll
            for (int jp = 0; jp < 4; jp++) {
                uint32_t bhi[4], blo[4];
                uint32_t off = (uint32_t)((wn + jp * 16) * 64 + kb) + b_off;
                LDSM_X4(bhi, st + 16384 + SWZ64(off));
                LDSM_X4(blo, st + 24576 + SWZ64(off));
                // product-major: same-acc MMAs are 4 apart (no RAW stalls)
                #pragma unroll
                for (int i = 0; i < 2; i++)
                    #pragma unroll
                    for (int jj = 0; jj < 2; jj++)
                        MMA16816(acc[i][jp * 2 + jj], ahi[i], (&bhi[jj * 2]));
                #pragma unroll
                for (int i = 0; i < 2; i++)
                    #pragma unroll
                    for (int jj = 0; jj < 2; jj++)
                        MMA16816(acc[i][jp * 2 + jj], ahi[i], (&blo[jj * 2]));
                #pragma unroll
                for (int i = 0; i < 2; i++)
                    #pragma unroll
                    for (int jj = 0; jj < 2; jj++)
                        MMA16816(acc[i][jp * 2 + jj], alo[i], (&bhi[jj * 2]));
            }
        }
        ++sidx; if (sidx >= 3) sidx = 0;
    }

    #pragma unroll
    for (int i = 0; i < 2; i++) {
        #pragma unroll
        for (int j = 0; j < 8; j++) {
            int r0 = rowBase + wm + i * 16 + (lane >> 2);
            int c0 = colBase + wn + j * 8 + (lane & 3) * 2;
            if (SPLIT) {
                #pragma unroll
                for (int hh = 0; hh < 2; hh++) {
                    float v0 = acc[i][j][hh * 2], v1 = acc[i][j][hh * 2 + 1];
                    __nv_bfloat162 h2 = __floats2bfloat162_rn(v0, v1);
                    float l0 = v0 - __bfloat162float(h2.x);
                    float l1 = v1 - __bfloat162float(h2.y);
                    size_t idx = ((size_t)(r0 + hh * 8) * N + c0) >> 1;
                    ((uint32_t*)Chi)[idx] = *(uint32_t*)&h2;
                    ((uint32_t*)Clo)[idx] = pack_bf2(l0, l1);
                }
            } else {
                *(float2*)&C[(size_t)r0 * N + c0]       = make_float2(acc[i][j][0], acc[i][j][1]);
                *(float2*)&C[(size_t)(r0 + 8) * N + c0] = make_float2(acc[i][j][2], acc[i][j][3]);
            }
        }
    }
}

// ---------------------------------------------------------------------------
// Flash attention, HMMA. CTA = 128 q rows of one (b,h); 8 warps x 16 rows.
// Bc=64: stage 32KB, 2 stages + Q 32KB = 96KB; single barrier/iter; 2 CTA/SM.
// ---------------------------------------------------------------------------
#define FST     32768
#define F_KHI   0
#define F_KLO   8192
#define F_VHI   16384
#define F_VLO   24576
#define FQ_OFF  (2 * FST)
#define FSMEM_TOTAL (2 * FST + 32768)

#define FLOAD_KV(sidx, c0b) do {                                               \
    uint32_t sb = sbase + (uint32_t)(sidx) * FST;                              \
    _Pragma("unroll")                                                          \
    for (int t_ = 0; t_ < 2; ++t_) {                                           \
        int v_ = tid + t_ * 256;                                               \
        int row_ = v_ >> 3, ch_ = v_ & 7;                                      \
        uint32_t sw_ = SWZ128((uint32_t)(row_ * 128 + ch_ * 16));              \
        size_t base_ = ((size_t)(bS + (c0b) + row_) * 3) * DIM + hHD + ch_ * 8;\
        CPA16(sb + F_KHI + sw_, (const char*)(qh + base_ + DIM));              \
        CPA16(sb + F_KLO + sw_, (const char*)(ql + base_ + DIM));              \
        CPA16(sb + F_VHI + sw_, (const char*)(qh + base_ + 2 * DIM));          \
        CPA16(sb + F_VLO + sw_, (const char*)(ql + base_ + 2 * DIM));          \
    }                                                                          \
} while (0)

__global__ __launch_bounds__(256, 2) void flash_mma(
    const __nv_bfloat16* __restrict__ qh, const __nv_bfloat16* __restrict__ ql,
    __nv_bfloat16* __restrict__ Ahi, __nv_bfloat16* __restrict__ Alo)
{
    extern __shared__ char smem[];
    const uint32_t sbase = smem_u32(smem);
    const int tid  = threadIdx.x;
    const int lane = tid & 31;
    const int wid  = tid >> 5;
    const int wrow = wid * 16;
    const int h  = blockIdx.y;
    const int b  = blockIdx.z;
    const int q0 = blockIdx.x * 128;
    const int bS  = b * SEQ;
    const int hHD = h * HD;

    const int mi = lane >> 3;
    const uint32_t a_row = (mi & 1) * 8 + (lane & 7);
    const uint32_t a_ch  = (mi >> 1) * 16;
    const uint32_t b_row = (mi >> 1) * 8 + (lane & 7);
    const uint32_t b_ch  = (mi & 1) * 16;

    // Q tile (once) + first KV stage
    {
        #pragma unroll
        for (int t_ = 0; t_ < 4; ++t_) {
            int v_ = tid + t_ * 256;
            int row_ = v_ >> 3, ch_ = v_ & 7;
            uint32_t sw_ = SWZ128((uint32_t)(row_ * 128 + ch_ * 16));
            size_t base_ = ((size_t)(bS + q0 + row_) * 3) * DIM + hHD + ch_ * 8;
            CPA16(sbase + FQ_OFF + sw_,         (const char*)(qh + base_));
            CPA16(sbase + FQ_OFF + 16384 + sw_, (const char*)(ql + base_));
        }
        FLOAD_KV(0, 0);
        CP_COMMIT();
    }

    float S[8][4];
    float O[8][4];
    #pragma unroll
    for (int j = 0; j < 8; j++)
        #pragma unroll
        for (int q = 0; q < 4; q++) O[j][q] = 0.f;
    float mA = -1e30f, mB = -1e30f, lA = 0.f, lB = 0.f;

    const int ntiles = SEQ / 64;   // 32

    for (int tI = 0; tI < ntiles; ++tI) {
        const int s = tI & 1;
        CP_WAIT0();
        __syncthreads();               // all warps done with compute(tI-1)
        if (tI + 1 < ntiles) { FLOAD_KV((tI + 1) & 1, (tI + 1) * 64); CP_COMMIT(); }

        const uint32_t st = sbase + (uint32_t)s * FST;

        // ---- S = Q K^T (3-product split, product-major) ----
        #pragma unroll
        for (int nb = 0; nb < 8; nb++)
            #pragma unroll
            for (int q = 0; q < 4; q++) S[nb][q] = 0.f;

        #pragma unroll
        for (int dks = 0; dks < 4; dks++) {
            uint32_t qhi[4], qlo[4];
            uint32_t qoff = SWZ128((uint32_t)((wrow + a_row) * 128 + dks * 32 + a_ch));
            LDSM_X4(qhi, sbase + FQ_OFF + qoff);
            LDSM_X4(qlo, sbase + FQ_OFF + 16384 + qoff);
            #pragma unroll
            for (int nbp = 0; nbp < 4; nbp++) {
                uint32_t khi[4], klo[4];
                uint32_t koff = SWZ128((uint32_t)((nbp * 16 + b_row) * 128 + dks * 32 + b_ch));
                LDSM_X4(khi, st + F_KHI + koff);
                LDSM_X4(klo, st + F_KLO + koff);
                float* s0 = S[nbp * 2 + 0];
                float* s1 = S[nbp * 2 + 1];
                MMA16816(s0, qhi, (&khi[0]));
                MMA16816(s1, qhi, (&khi[2]));
                MMA16816(s0, qhi, (&klo[0]));
                MMA16816(s1, qhi, (&klo[2]));
                MMA16816(s0, qlo, (&khi[0]));
                MMA16816(s1, qlo, (&khi[2]));
            }
        }

        // ---- online softmax (base-2 domain) ----
        #pragma unroll
        for (int nb = 0; nb < 8; nb++)
            #pragma unroll
            for (int q = 0; q < 4; q++) S[nb][q] *= SC2;

        float mxA = -1e30f, mxB = -1e30f;
        #pragma unroll
        for (int nb = 0; nb < 8; nb++) {
            mxA = fmaxf(mxA, fmaxf(S[nb][0], S[nb][1]));
            mxB = fmaxf(mxB, fmaxf(S[nb][2], S[nb][3]));
        }
        #pragma unroll
        for (int d = 1; d <= 2; d <<= 1) {
            mxA = fmaxf(mxA, __shfl_xor_sync(0xffffffffu, mxA, d));
            mxB = fmaxf(mxB, __shfl_xor_sync(0xffffffffu, mxB, d));
        }
        float mAn = fmaxf(mA, mxA), mBn = fmaxf(mB, mxB);
        float fA = ex2f(mA - mAn),  fB = ex2f(mB - mBn);
        float sA = 0.f, sB = 0.f;
        #pragma unroll
        for (int nb = 0; nb < 8; nb++) {
            float p0 = ex2f(S[nb][0] - mAn), p1 = ex2f(S[nb][1] - mAn);
            float p2 = ex2f(S[nb][2] - mBn), p3 = ex2f(S[nb][3] - mBn);
            S[nb][0] = p0; S[nb][1] = p1; S[nb][2] = p2; S[nb][3] = p3;
            sA += p0 + p1; sB += p2 + p3;
        }
        #pragma unroll
        for (int d = 1; d <= 2; d <<= 1) {
            sA += __shfl_xor_sync(0xffffffffu, sA, d);
            sB += __shfl_xor_sync(0xffffffffu, sB, d);
        }
        lA = lA * fA + sA;  lB = lB * fB + sB;
        mA = mAn;           mB = mBn;
        #pragma unroll
        for (int j = 0; j < 8; j++) {
            O[j][0] *= fA; O[j][1] *= fA; O[j][2] *= fB; O[j][3] *= fB;
        }

        // ---- O += P V (3-product split; product-major) ----
        #pragma unroll
        for (int ks = 0; ks < 4; ks++) {
            uint32_t ph[4], pl[4];
            #pragma unroll
            for (int u = 0; u < 4; u++) {
                const float* sv = S[ks * 2 + (u >> 1)];
                float x0 = sv[(u & 1) * 2], x1 = sv[(u & 1) * 2 + 1];
                __nv_bfloat162 h2 = __floats2bfloat162_rn(x0, x1);
                ph[u] = *(uint32_t*)&h2;
                pl[u] = pack_bf2(x0 - __bfloat162float(h2.x), x1 - __bfloat162float(h2.y));
            }
            #pragma unroll
            for (int dg = 0; dg < 4; dg++) {
                uint32_t vh[4], vl[4];
                uint32_t voff = SWZ128((uint32_t)((ks * 16 + a_row) * 128 + dg * 32 + a_ch));
                LDSM_X4T(vh, st + F_VHI + voff);
                LDSM_X4T(vl, st + F_VLO + voff);
                float* o0 = O[dg * 2 + 0];
                float* o1 = O[dg * 2 + 1];
                MMA16816(o0, ph, (&vh[0]));
                MMA16816(o1, ph, (&vh[2]));
                MMA16816(o0, ph, (&vl[0]));
                MMA16816(o1, ph, (&vl[2]));
                MMA16816(o0, pl, (&vh[0]));
                MMA16816(o1, pl, (&vh[2]));
            }
        }
    }

    // ---- epilogue: normalize, split to bf16 hi/lo, store ----
    float invA = 1.f / lA, invB = 1.f / lB;
    int rA = bS + q0 + wrow + (lane >> 2);
    int rB = rA + 8;
    #pragma unroll
    for (int j = 0; j < 8; j++) {
        int d0 = j * 8 + (lane & 3) * 2;
        float a0 = O[j][0] * invA, a1 = O[j][1] * invA;
        float b0 = O[j][2] * invB, b1 = O[j][3] * invB;
        __nv_bfloat162 hA = __floats2bfloat162_rn(a0, a1);
        __nv_bfloat162 hB = __floats2bfloat162_rn(b0, b1);
        size_t iA = ((size_t)rA * DIM + hHD + d0) >> 1;
        size_t iB = ((size_t)rB * DIM + hHD + d0) >> 1;
        ((uint32_t*)Ahi)[iA] = *(uint32_t*)&hA;
        ((uint32_t*)Ahi)[iB] = *(uint32_t*)&hB;
        ((uint32_t*)Alo)[iA] = pack_bf2(a0 - __bfloat162float(hA.x), a1 - __bfloat162float(hA.y));
        ((uint32_t*)Alo)[iB] = pack_bf2(b0 - __bfloat162float(hB.x), b1 - __bfloat162float(hB.y));
    }
}

// ---------------------------------------------------------------------------
extern "C" void kernel_launch(void* const* d_in, const int* in_sizes, int n_in,
                              void* d_out, int out_size)
{
    const float* x     = (const float*)d_in[0];
    const float* Wqkv  = (const float*)d_in[1];
    const float* Wproj = (const float*)d_in[2];
    float* out = (float*)d_out;

    __nv_bfloat16 *xhi, *xlo, *qh, *ql, *ahi, *alo, *wqhi, *wqlo, *wphi, *wplo;
    cudaGetSymbolAddress((void**)&xhi,  g_xhi);
    cudaGetSymbolAddress((void**)&xlo,  g_xlo);
    cudaGetSymbolAddress((void**)&qh,   g_qh);
    cudaGetSymbolAddress((void**)&ql,   g_ql);
    cudaGetSymbolAddress((void**)&ahi,  g_ahi);
    cudaGetSymbolAddress((void**)&alo,  g_alo);
    cudaGetSymbolAddress((void**)&wqhi, g_wqhi);
    cudaGetSymbolAddress((void**)&wqlo, g_wqlo);
    cudaGetSymbolAddress((void**)&wphi, g_wphi);
    cudaGetSymbolAddress((void**)&wplo, g_wplo);

    const int M = BATCH * SEQ;          // 4096

    cudaFuncSetAttribute(gemm_mma<true>,  cudaFuncAttributeMaxDynamicSharedMemorySize, GSMEM_TOTAL);
    cudaFuncSetAttribute(gemm_mma<false>, cudaFuncAttributeMaxDynamicSharedMemorySize, GSMEM_TOTAL);
    cudaFuncSetAttribute(flash_mma,       cudaFuncAttributeMaxDynamicSharedMemorySize, FSMEM_TOTAL);

    // 0) splits
    split_kernel<<<(M * DIM / 4 + 255) / 256, 256>>>(x, xhi, xlo, M * DIM / 4);
    {
        dim3 g1(3 * DIM / 32, DIM / 32);
        transpose_split<<<g1, 256>>>(Wqkv, wqhi, wqlo, DIM, 3 * DIM);
        dim3 g2(DIM / 32, DIM / 32);
        transpose_split<<<g2, 256>>>(Wproj, wphi, wplo, DIM, DIM);
    }

    // 1) qkv = x @ Wqkv -> bf16 hi/lo directly
    {
        dim3 grid(3 * DIM / 128, M / 128);
        gemm_mma<true><<<grid, 256, GSMEM_TOTAL>>>(xhi, xlo, wqhi, wqlo,
                                                   nullptr, qh, ql, M, 3 * DIM, DIM);
    }

    // 2) flash attention (HMMA) -> bf16 hi/lo directly
    {
        dim3 grid(SEQ / 128, NHEAD, BATCH);
        flash_mma<<<grid, 256, FSMEM_TOTAL>>>(qh, ql, ahi, alo);
    }

    // 3) out = attn @ Wproj (fp32 out)
    {
        dim3 grid(DIM / 128, M / 128);
        gemm_mma<false><<<grid, 256, GSMEM_TOTAL>>>(ahi, alo, wphi, wplo,
                                                    out, nullptr, nullptr, M, DIM, DIM);
    }
}

// round 8
// speedup vs baseline: 4.0408x; 1.0020x over previous
#include <cuda_runtime.h>
#include <cuda_bf16.h>
#include <cstdint>
#include <cstddef>

#define BATCH 2
#define SEQ   2048
#define DIM   1024
#define NHEAD 16
#define HD    64
// SCALE * log2(e): logits kept in base-2 domain (folded into Q at QKV epilogue)
#define SC2   0.18033688011112042f

// ---------------------------------------------------------------------------
// Scratch (allocation-free rule: __device__ globals)
// ---------------------------------------------------------------------------
__device__ __nv_bfloat16 g_xhi[(size_t)BATCH * SEQ * DIM];
__device__ __nv_bfloat16 g_xlo[(size_t)BATCH * SEQ * DIM];
__device__ __nv_bfloat16 g_qh [(size_t)BATCH * SEQ * 3 * DIM];   // qkv hi
__device__ __nv_bfloat16 g_ql [(size_t)BATCH * SEQ * 3 * DIM];   // qkv lo
__device__ __nv_bfloat16 g_ahi[(size_t)BATCH * SEQ * DIM];       // attn hi
__device__ __nv_bfloat16 g_alo[(size_t)BATCH * SEQ * DIM];       // attn lo
__device__ __nv_bfloat16 g_wqhi[(size_t)3 * DIM * DIM];          // [3072,1024] K-major
__device__ __nv_bfloat16 g_wqlo[(size_t)3 * DIM * DIM];
__device__ __nv_bfloat16 g_wphi[(size_t)DIM * DIM];
__device__ __nv_bfloat16 g_wplo[(size_t)DIM * DIM];

// ---------------------------------------------------------------------------
// Portable PTX helpers
// ---------------------------------------------------------------------------
__device__ __forceinline__ uint32_t smem_u32(const void* p) {
    uint32_t a;
    asm("{ .reg .u64 t; cvta.to.shared.u64 t, %1; cvt.u32.u64 %0, t; }" : "=r"(a) : "l"(p));
    return a;
}
#define CPA16(dst, src) \
    asm volatile("cp.async.cg.shared.global [%0], [%1], 16;" :: "r"(dst), "l"(src) : "memory")
#define CP_COMMIT() asm volatile("cp.async.commit_group;" ::: "memory")
#define CP_WAIT0()  asm volatile("cp.async.wait_group 0;" ::: "memory")
#define CP_WAIT1()  asm volatile("cp.async.wait_group 1;" ::: "memory")

#define LDSM_X4(r, addr) \
    asm volatile("ldmatrix.sync.aligned.m8n8.x4.shared.b16 {%0,%1,%2,%3}, [%4];" \
        : "=r"((r)[0]), "=r"((r)[1]), "=r"((r)[2]), "=r"((r)[3]) : "r"(addr))
#define LDSM_X4T(r, addr) \
    asm volatile("ldmatrix.sync.aligned.m8n8.x4.trans.shared.b16 {%0,%1,%2,%3}, [%4];" \
        : "=r"((r)[0]), "=r"((r)[1]), "=r"((r)[2]), "=r"((r)[3]) : "r"(addr))

#define MMA16816(c, a, b) \
    asm volatile("mma.sync.aligned.m16n8k16.row.col.f32.bf16.bf16.f32 " \
        "{%0,%1,%2,%3}, {%4,%5,%6,%7}, {%8,%9}, {%0,%1,%2,%3};" \
        : "+f"((c)[0]), "+f"((c)[1]), "+f"((c)[2]), "+f"((c)[3]) \
        : "r"((a)[0]), "r"((a)[1]), "r"((a)[2]), "r"((a)[3]), "r"((b)[0]), "r"((b)[1]))

#define SWZ64(off)  ((off) ^ (((off) >> 3) & 0x30))
#define SWZ128(off) ((off) ^ (((off) >> 3) & 0x70))

__device__ __forceinline__ float ex2f(float x) {
    float y; asm("ex2.approx.ftz.f32 %0, %1;" : "=f"(y) : "f"(x)); return y;
}
__device__ __forceinline__ uint32_t pack_bf2(float lo, float hi) {
    __nv_bfloat162 h = __floats2bfloat162_rn(lo, hi);
    return *(uint32_t*)&h;
}

// ---------------------------------------------------------------------------
// Preprocessing
// ---------------------------------------------------------------------------
__global__ __launch_bounds__(256) void split_kernel(
    const float* __restrict__ X, __nv_bfloat16* __restrict__ hi,
    __nv_bfloat16* __restrict__ lo, int n4)
{
    int i = blockIdx.x * blockDim.x + threadIdx.x;
    if (i >= n4) return;
    float4 v = ((const float4*)X)[i];
    __nv_bfloat16 h[4], l[4];
    float f[4] = {v.x, v.y, v.z, v.w};
    #pragma unroll
    for (int j = 0; j < 4; j++) {
        h[j] = __float2bfloat16(f[j]);
        l[j] = __float2bfloat16(f[j] - __bfloat162float(h[j]));
    }
    ((uint2*)hi)[i] = *(uint2*)h;
    ((uint2*)lo)[i] = *(uint2*)l;
}

__global__ __launch_bounds__(256) void transpose_split(
    const float* __restrict__ W, __nv_bfloat16* __restrict__ Thi,
    __nv_bfloat16* __restrict__ Tlo, int K, int N)
{
    __shared__ float tile[32][33];
    int tx = threadIdx.x & 31, ty = threadIdx.x >> 5;
    int k0 = blockIdx.y * 32, n0 = blockIdx.x * 32;
    #pragma unroll
    for (int i = 0; i < 32; i += 8)
        tile[ty + i][tx] = W[(size_t)(k0 + ty + i) * N + n0 + tx];
    __syncthreads();
    #pragma unroll
    for (int i = 0; i < 32; i += 8) {
        float v = tile[tx][ty + i];
        __nv_bfloat16 h = __float2bfloat16(v);
        __nv_bfloat16 l = __float2bfloat16(v - __bfloat162float(h));
        size_t o = (size_t)(n0 + ty + i) * K + k0 + tx;
        Thi[o] = h; Tlo[o] = l;
    }
}

// ---------------------------------------------------------------------------
// HMMA bf16-split GEMM: C = A[M,K] @ T[N,K]^T, fp32 or bf16-hi/lo output
// CTA 128x128, BK=32, 3-stage cp.async, single barrier/iter, 2 CTAs/SM.
// SPLIT epilogue scales by SC2 for the Q columns (colBase < DIM).
// ---------------------------------------------------------------------------
#define GST 32768
#define GSMEM_TOTAL (3 * GST)

#define LOAD_STAGE(sidx, kc) do {                                              \
    uint32_t sb = sbase + (uint32_t)(sidx) * GST;                              \
    _Pragma("unroll")                                                          \
    for (int t_ = 0; t_ < 2; ++t_) {                                           \
        int v_ = tid + t_ * 256;                                               \
        int row_ = v_ >> 2, cb_ = v_ & 3;                                      \
        uint32_t sw_ = SWZ64((uint32_t)(row_ * 64 + cb_ * 16));                \
        size_t gA_ = (size_t)(rowBase + row_) * K + (kc) + cb_ * 8;            \
        size_t gB_ = (size_t)(colBase + row_) * K + (kc) + cb_ * 8;            \
        CPA16(sb + sw_,         (const char*)(Ahi + gA_));                     \
        CPA16(sb + 8192  + sw_, (const char*)(Alo + gA_));                     \
        CPA16(sb + 16384 + sw_, (const char*)(Bhi + gB_));                     \
        CPA16(sb + 24576 + sw_, (const char*)(Blo + gB_));                     \
    }                                                                          \
} while (0)

template <bool SPLIT>
__global__ __launch_bounds__(256, 2) void gemm_mma(
    const __nv_bfloat16* __restrict__ Ahi, const __nv_bfloat16* __restrict__ Alo,
    const __nv_bfloat16* __restrict__ Bhi, const __nv_bfloat16* __restrict__ Blo,
    float* __restrict__ C, __nv_bfloat16* __restrict__ Chi,
    __nv_bfloat16* __restrict__ Clo, int M, int N, int K)
{
    extern __shared__ char smem[];
    const uint32_t sbase = smem_u32(smem);
    const int tid  = threadIdx.x;
    const int lane = tid & 31;
    const int wid  = tid >> 5;
    const int wm = (wid & 3) * 32;
    const int wn = (wid >> 2) * 64;
    const int rowBase = blockIdx.y * 128;
    const int colBase = blockIdx.x * 128;

    const int mi = lane >> 3;
    const uint32_t a_off = (uint32_t)((((mi & 1) * 8 + (lane & 7)) * 64) + (mi >> 1) * 16);
    const uint32_t b_off = (uint32_t)((((mi >> 1) * 8 + (lane & 7)) * 64) + (mi & 1) * 16);

    float acc[2][8][4];
    #pragma unroll
    for (int i = 0; i < 2; i++)
        #pragma unroll
        for (int j = 0; j < 8; j++)
            #pragma unroll
            for (int q = 0; q < 4; q++) acc[i][j][q] = 0.f;

    const int nk = K / 32;                 // 32
    LOAD_STAGE(0, 0);  CP_COMMIT();
    LOAD_STAGE(1, 32); CP_COMMIT();

    int sidx = 0;                          // stage of chunk c (mod 3)
    for (int c = 0; c < nk; ++c) {
        if (c + 1 < nk) { CP_WAIT1(); } else { CP_WAIT0(); }
        __syncthreads();                   // all warps done with compute(c-1)
        if (c + 2 < nk) {
            int ns = sidx + 2; if (ns >= 3) ns -= 3;
            LOAD_STAGE(ns, (c + 2) * 32);
            CP_COMMIT();
        }

        const uint32_t st = sbase + (uint32_t)sidx * GST;
        #pragma unroll
        for (int kb = 0; kb < 64; kb += 32) {
            uint32_t ahi[2][4], alo[2][4];
            #pragma unroll
            for (int i = 0; i < 2; i++) {
                uint32_t off = (uint32_t)((wm + i * 16) * 64 + kb) + a_off;
                LDSM_X4(ahi[i], st + SWZ64(off));
                LDSM_X4(alo[i], st + 8192 + SWZ64(off));
            }
            #pragma unroll
            for (int jp = 0; jp < 4; jp++) {
                uint32_t bhi[4], blo[4];
                uint32_t off = (uint32_t)((wn + jp * 16) * 64 + kb) + b_off;
                LDSM_X4(bhi, st + 16384 + SWZ64(off));
                LDSM_X4(blo, st + 24576 + SWZ64(off));
                #pragma unroll
                for (int i = 0; i < 2; i++)
                    #pragma unroll
                    for (int jj = 0; jj < 2; jj++)
                        MMA16816(acc[i][jp * 2 + jj], ahi[i], (&bhi[jj * 2]));
                #pragma unroll
                for (int i = 0; i < 2; i++)
                    #pragma unroll
                    for (int jj = 0; jj < 2; jj++)
                        MMA16816(acc[i][jp * 2 + jj], ahi[i], (&blo[jj * 2]));
                #pragma unroll
                for (int i = 0; i < 2; i++)
                    #pragma unroll
                    for (int jj = 0; jj < 2; jj++)
                        MMA16816(acc[i][jp * 2 + jj], alo[i], (&bhi[jj * 2]));
            }
        }
        ++sidx; if (sidx >= 3) sidx = 0;
    }

    // SC2 folded into Q columns (SPLIT path only; colBase uniform per CTA)
    const float oscale = (SPLIT && colBase < DIM) ? SC2 : 1.0f;

    #pragma unroll
    for (int i = 0; i < 2; i++) {
        #pragma unroll
        for (int j = 0; j < 8; j++) {
            int r0 = rowBase + wm + i * 16 + (lane >> 2);
            int c0 = colBase + wn + j * 8 + (lane & 3) * 2;
            if (SPLIT) {
                #pragma unroll
                for (int hh = 0; hh < 2; hh++) {
                    float v0 = acc[i][j][hh * 2] * oscale, v1 = acc[i][j][hh * 2 + 1] * oscale;
                    __nv_bfloat162 h2 = __floats2bfloat162_rn(v0, v1);
                    float l0 = v0 - __bfloat162float(h2.x);
                    float l1 = v1 - __bfloat162float(h2.y);
                    size_t idx = ((size_t)(r0 + hh * 8) * N + c0) >> 1;
                    ((uint32_t*)Chi)[idx] = *(uint32_t*)&h2;
                    ((uint32_t*)Clo)[idx] = pack_bf2(l0, l1);
                }
            } else {
                *(float2*)&C[(size_t)r0 * N + c0]       = make_float2(acc[i][j][0], acc[i][j][1]);
                *(float2*)&C[(size_t)(r0 + 8) * N + c0] = make_float2(acc[i][j][2], acc[i][j][3]);
            }
        }
    }
}

// ---------------------------------------------------------------------------
// Flash attention, HMMA. CTA = 128 q rows of one (b,h); 8 warps x 16 rows.
// Bc=64: stage 32KB, 2 stages + Q 32KB = 96KB; 2 CTAs/SM.
// Softmax exp interleaved with PV MMAs (MUFU overlaps tensor).
// Q already scaled by SC2 at the QKV-GEMM epilogue.
// ---------------------------------------------------------------------------
#define FST     32768
#define F_KHI   0
#define F_KLO   8192
#define F_VHI   16384
#define F_VLO   24576
#define FQ_OFF  (2 * FST)
#define FSMEM_TOTAL (2 * FST + 32768)

#define FLOAD_KV(sidx, c0b) do {                                               \
    uint32_t sb = sbase + (uint32_t)(sidx) * FST;                              \
    _Pragma("unroll")                                                          \
    for (int t_ = 0; t_ < 2; ++t_) {                                           \
        int v_ = tid + t_ * 256;                                               \
        int row_ = v_ >> 3, ch_ = v_ & 7;                                      \
        uint32_t sw_ = SWZ128((uint32_t)(row_ * 128 + ch_ * 16));              \
        size_t base_ = ((size_t)(bS + (c0b) + row_) * 3) * DIM + hHD + ch_ * 8;\
        CPA16(sb + F_KHI + sw_, (const char*)(qh + base_ + DIM));              \
        CPA16(sb + F_KLO + sw_, (const char*)(ql + base_ + DIM));              \
        CPA16(sb + F_VHI + sw_, (const char*)(qh + base_ + 2 * DIM));          \
        CPA16(sb + F_VLO + sw_, (const char*)(ql + base_ + 2 * DIM));          \
    }                                                                          \
} while (0)

__global__ __launch_bounds__(256, 2) void flash_mma(
    const __nv_bfloat16* __restrict__ qh, const __nv_bfloat16* __restrict__ ql,
    __nv_bfloat16* __restrict__ Ahi, __nv_bfloat16* __restrict__ Alo)
{
    extern __shared__ char smem[];
    const uint32_t sbase = smem_u32(smem);
    const int tid  = threadIdx.x;
    const int lane = tid & 31;
    const int wid  = tid >> 5;
    const int wrow = wid * 16;
    const int h  = blockIdx.y;
    const int b  = blockIdx.z;
    const int q0 = blockIdx.x * 128;
    const int bS  = b * SEQ;
    const int hHD = h * HD;

    const int mi = lane >> 3;
    const uint32_t a_row = (mi & 1) * 8 + (lane & 7);
    const uint32_t a_ch  = (mi >> 1) * 16;
    const uint32_t b_row = (mi >> 1) * 8 + (lane & 7);
    const uint32_t b_ch  = (mi & 1) * 16;

    // Q tile (once) + first KV stage
    {
        #pragma unroll
        for (int t_ = 0; t_ < 4; ++t_) {
            int v_ = tid + t_ * 256;
            int row_ = v_ >> 3, ch_ = v_ & 7;
            uint32_t sw_ = SWZ128((uint32_t)(row_ * 128 + ch_ * 16));
            size_t base_ = ((size_t)(bS + q0 + row_) * 3) * DIM + hHD + ch_ * 8;
            CPA16(sbase + FQ_OFF + sw_,         (const char*)(qh + base_));
            CPA16(sbase + FQ_OFF + 16384 + sw_, (const char*)(ql + base_));
        }
        FLOAD_KV(0, 0);
        CP_COMMIT();
    }

    float S[8][4];
    float O[8][4];
    #pragma unroll
    for (int j = 0; j < 8; j++)
        #pragma unroll
        for (int q = 0; q < 4; q++) O[j][q] = 0.f;
    float mA = -1e30f, mB = -1e30f, lA = 0.f, lB = 0.f;

    const int ntiles = SEQ / 64;   // 32

    for (int tI = 0; tI < ntiles; ++tI) {
        const int s = tI & 1;
        CP_WAIT0();
        __syncthreads();               // all warps done with compute(tI-1)
        if (tI + 1 < ntiles) { FLOAD_KV((tI + 1) & 1, (tI + 1) * 64); CP_COMMIT(); }

        const uint32_t st = sbase + (uint32_t)s * FST;

        // ---- S = Q K^T (3-product split; logits in base-2 domain already) ----
        #pragma unroll
        for (int nb = 0; nb < 8; nb++)
            #pragma unroll
            for (int q = 0; q < 4; q++) S[nb][q] = 0.f;

        #pragma unroll
        for (int dks = 0; dks < 4; dks++) {
            uint32_t qhi[4], qlo[4];
            uint32_t qoff = SWZ128((uint32_t)((wrow + a_row) * 128 + dks * 32 + a_ch));
            LDSM_X4(qhi, sbase + FQ_OFF + qoff);
            LDSM_X4(qlo, sbase + FQ_OFF + 16384 + qoff);
            #pragma unroll
            for (int nbp = 0; nbp < 4; nbp++) {
                uint32_t khi[4], klo[4];
                uint32_t koff = SWZ128((uint32_t)((nbp * 16 + b_row) * 128 + dks * 32 + b_ch));
                LDSM_X4(khi, st + F_KHI + koff);
                LDSM_X4(klo, st + F_KLO + koff);
                float* s0 = S[nbp * 2 + 0];
                float* s1 = S[nbp * 2 + 1];
                MMA16816(s0, qhi, (&khi[0]));
                MMA16816(s1, qhi, (&khi[2]));
                MMA16816(s0, qhi, (&klo[0]));
                MMA16816(s1, qhi, (&klo[2]));
                MMA16816(s0, qlo, (&khi[0]));
                MMA16816(s1, qlo, (&khi[2]));
            }
        }

        // ---- row max + O rescale (before exp so exp can interleave with PV) ----
        float mxA = -1e30f, mxB = -1e30f;
        #pragma unroll
        for (int nb = 0; nb < 8; nb++) {
            mxA = fmaxf(mxA, fmaxf(S[nb][0], S[nb][1]));
            mxB = fmaxf(mxB, fmaxf(S[nb][2], S[nb][3]));
        }
        #pragma unroll
        for (int d = 1; d <= 2; d <<= 1) {
            mxA = fmaxf(mxA, __shfl_xor_sync(0xffffffffu, mxA, d));
            mxB = fmaxf(mxB, __shfl_xor_sync(0xffffffffu, mxB, d));
        }
        float mAn = fmaxf(mA, mxA), mBn = fmaxf(mB, mxB);
        float fA = ex2f(mA - mAn),  fB = ex2f(mB - mBn);
        #pragma unroll
        for (int j = 0; j < 8; j++) {
            O[j][0] *= fA; O[j][1] *= fA; O[j][2] *= fB; O[j][3] *= fB;
        }

        // ---- interleaved: exp + pack + PV MMAs per ks block ----
        float sA = 0.f, sB = 0.f;
        #pragma unroll
        for (int ks = 0; ks < 4; ks++) {
            float pv[2][4];
            #pragma unroll
            for (int jj = 0; jj < 2; jj++) {
                const float* sv = S[ks * 2 + jj];
                pv[jj][0] = ex2f(sv[0] - mAn);
                pv[jj][1] = ex2f(sv[1] - mAn);
                pv[jj][2] = ex2f(sv[2] - mBn);
                pv[jj][3] = ex2f(sv[3] - mBn);
                sA += pv[jj][0] + pv[jj][1];
                sB += pv[jj][2] + pv[jj][3];
            }
            uint32_t ph[4], pl[4];
            #pragma unroll
            for (int u = 0; u < 4; u++) {
                const float* sv = pv[u >> 1];
                float x0 = sv[(u & 1) * 2], x1 = sv[(u & 1) * 2 + 1];
                __nv_bfloat162 h2 = __floats2bfloat162_rn(x0, x1);
                ph[u] = *(uint32_t*)&h2;
                pl[u] = pack_bf2(x0 - __bfloat162float(h2.x), x1 - __bfloat162float(h2.y));
            }
            #pragma unroll
            for (int dg = 0; dg < 4; dg++) {
                uint32_t vh[4], vl[4];
                uint32_t voff = SWZ128((uint32_t)((ks * 16 + a_row) * 128 + dg * 32 + a_ch));
                LDSM_X4T(vh, st + F_VHI + voff);
                LDSM_X4T(vl, st + F_VLO + voff);
                float* o0 = O[dg * 2 + 0];
                float* o1 = O[dg * 2 + 1];
                MMA16816(o0, ph, (&vh[0]));
                MMA16816(o1, ph, (&vh[2]));
                MMA16816(o0, ph, (&vl[0]));
                MMA16816(o1, ph, (&vl[2]));
                MMA16816(o0, pl, (&vh[0]));
                MMA16816(o1, pl, (&vh[2]));
            }
        }
        #pragma unroll
        for (int d = 1; d <= 2; d <<= 1) {
            sA += __shfl_xor_sync(0xffffffffu, sA, d);
            sB += __shfl_xor_sync(0xffffffffu, sB, d);
        }
        lA = lA * fA + sA;  lB = lB * fB + sB;
        mA = mAn;           mB = mBn;
    }

    // ---- epilogue: normalize, split to bf16 hi/lo, store ----
    float invA = 1.f / lA, invB = 1.f / lB;
    int rA = bS + q0 + wrow + (lane >> 2);
    int rB = rA + 8;
    #pragma unroll
    for (int j = 0; j < 8; j++) {
        int d0 = j * 8 + (lane & 3) * 2;
        float a0 = O[j][0] * invA, a1 = O[j][1] * invA;
        float b0 = O[j][2] * invB, b1 = O[j][3] * invB;
        __nv_bfloat162 hA = __floats2bfloat162_rn(a0, a1);
        __nv_bfloat162 hB = __floats2bfloat162_rn(b0, b1);
        size_t iA = ((size_t)rA * DIM + hHD + d0) >> 1;
        size_t iB = ((size_t)rB * DIM + hHD + d0) >> 1;
        ((uint32_t*)Ahi)[iA] = *(uint32_t*)&hA;
        ((uint32_t*)Ahi)[iB] = *(uint32_t*)&hB;
        ((uint32_t*)Alo)[iA] = pack_bf2(a0 - __bfloat162float(hA.x), a1 - __bfloat162float(hA.y));
        ((uint32_t*)Alo)[iB] = pack_bf2(b0 - __bfloat162float(hB.x), b1 - __bfloat162float(hB.y));
    }
}

// ---------------------------------------------------------------------------
extern "C" void kernel_launch(void* const* d_in, const int* in_sizes, int n_in,
                              void* d_out, int out_size)
{
    const float* x     = (const float*)d_in[0];
    const float* Wqkv  = (const float*)d_in[1];
    const float* Wproj = (const float*)d_in[2];
    float* out = (float*)d_out;

    __nv_bfloat16 *xhi, *xlo, *qh, *ql, *ahi, *alo, *wqhi, *wqlo, *wphi, *wplo;
    cudaGetSymbolAddress((void**)&xhi,  g_xhi);
    cudaGetSymbolAddress((void**)&xlo,  g_xlo);
    cudaGetSymbolAddress((void**)&qh,   g_qh);
    cudaGetSymbolAddress((void**)&ql,   g_ql);
    cudaGetSymbolAddress((void**)&ahi,  g_ahi);
    cudaGetSymbolAddress((void**)&alo,  g_alo);
    cudaGetSymbolAddress((void**)&wqhi, g_wqhi);
    cudaGetSymbolAddress((void**)&wqlo, g_wqlo);
    cudaGetSymbolAddress((void**)&wphi, g_wphi);
    cudaGetSymbolAddress((void**)&wplo, g_wplo);

    const int M = BATCH * SEQ;          // 4096

    cudaFuncSetAttribute(gemm_mma<true>,  cudaFuncAttributeMaxDynamicSharedMemorySize, GSMEM_TOTAL);
    cudaFuncSetAttribute(gemm_mma<false>, cudaFuncAttributeMaxDynamicSharedMemorySize, GSMEM_TOTAL);
    cudaFuncSetAttribute(flash_mma,       cudaFuncAttributeMaxDynamicSharedMemorySize, FSMEM_TOTAL);

    // 0) splits
    split_kernel<<<(M * DIM / 4 + 255) / 256, 256>>>(x, xhi, xlo, M * DIM / 4);
    {
        dim3 g1(3 * DIM / 32, DIM / 32);
        transpose_split<<<g1, 256>>>(Wqkv, wqhi, wqlo, DIM, 3 * DIM);
        dim3 g2(DIM / 32, DIM / 32);
        transpose_split<<<g2, 256>>>(Wproj, wphi, wplo, DIM, DIM);
    }

    // 1) qkv = x @ Wqkv -> bf16 hi/lo directly (Q columns pre-scaled by SC2)
    {
        dim3 grid(3 * DIM / 128, M / 128);
        gemm_mma<true><<<grid, 256, GSMEM_TOTAL>>>(xhi, xlo, wqhi, wqlo,
                                                   nullptr, qh, ql, M, 3 * DIM, DIM);
    }

    // 2) flash attention (HMMA) -> bf16 hi/lo directly
    {
        dim3 grid(SEQ / 128, NHEAD, BATCH);
        flash_mma<<<grid, 256, FSMEM_TOTAL>>>(qh, ql, ahi, alo);
    }

    // 3) out = attn @ Wproj (fp32 out)
    {
        dim3 grid(DIM / 128, M / 128);
        gemm_mma<false><<<grid, 256, GSMEM_TOTAL>>>(ahi, alo, wphi, wplo,
                                                    out, nullptr, nullptr, M, DIM, DIM);
    }
}